// round 13
// baseline (speedup 1.0000x reference)
#include <cuda_runtime.h>
#include <math.h>
#include <stddef.h>

#define EPSR 1e-8f
// 1/sqrt(1 + 1e-5)
#define BN_SCALE 0.99999500003749969f
#define LOG2PI 1.8378770664093454836f

// ---------------------------------------------------------------------------
// Scratch buffers (device globals; no allocation allowed)
// ---------------------------------------------------------------------------
__device__ float g_buf1 [32*256*14*14];
__device__ float g_bufA [32*16*12*12];
__device__ float g_bufP [32*256*12*12];
__device__ float g_bufA2[32*16*6*6];
__device__ float g_bufP2[32*256*6*6];
__device__ float g_bufA3[32*16*6*6];
__device__ float g_bufP3[32*256*6*6];
__device__ float g_bufFC[32*25*10];

// ---------------------------------------------------------------------------
// conv1: x(32,3,32,32) * w(256,3,5,5) stride2 VALID -> (32,256,14,14), + bn
// ---------------------------------------------------------------------------
__global__ void conv1_kernel(const float* __restrict__ x,
                             const float* __restrict__ w,
                             const float* __restrict__ g,
                             const float* __restrict__ b,
                             float* __restrict__ out)
{
    __shared__ float sIn[3*32*33];
    const int n = blockIdx.x, cot = blockIdx.y;
    const int tid = threadIdx.x;

    for (int idx = tid; idx < 3*32*32; idx += 224) {
        int ci = idx >> 10, rem = idx & 1023, r = rem >> 5, c = rem & 31;
        sIn[(ci*32 + r)*33 + c] = x[n*3072 + idx];
    }
    __syncthreads();

    const int co_l = tid / 14, oy = tid % 14;
    const int co = cot*16 + co_l;

    float acc[14];
#pragma unroll
    for (int i = 0; i < 14; i++) acc[i] = 0.f;

    const float* wp = w + co*75;
#pragma unroll
    for (int ci = 0; ci < 3; ci++) {
#pragma unroll
        for (int kh = 0; kh < 5; kh++) {
            const float* row = sIn + (ci*32 + oy*2 + kh)*33;
#pragma unroll
            for (int kw = 0; kw < 5; kw++) {
                float wv = wp[(ci*5 + kh)*5 + kw];
#pragma unroll
                for (int ox = 0; ox < 14; ox++)
                    acc[ox] = fmaf(wv, row[ox*2 + kw], acc[ox]);
            }
        }
    }
    const float sc = BN_SCALE * g[co], bi = b[co];
    float* op = out + (((size_t)n*256 + co)*14 + oy)*14;
#pragma unroll
    for (int ox = 0; ox < 14; ox++) op[ox] = acc[ox]*sc + bi;
}

// ---------------------------------------------------------------------------
// conv3 combined: 3x3 conv over buf1 (N,256,14,14) -> 12x12 + bn.
//   blockIdx.y in [0,4): convp tile (NCO=4: co, co+16, co+32, co+48)
//   blockIdx.y == 4    : conva (16 channels, sigmoid)
//   smem pitch 14 plain, scalar row loads (measured-good inner loop).
// ---------------------------------------------------------------------------
__global__ void conv3_both_kernel(const float* __restrict__ in,
                                  const float* __restrict__ wp_,
                                  const float* __restrict__ gp,
                                  const float* __restrict__ bp,
                                  const float* __restrict__ wa_,
                                  const float* __restrict__ ga,
                                  const float* __restrict__ ba_,
                                  float* __restrict__ outp,
                                  float* __restrict__ outa)
{
    extern __shared__ float sIn[];   // 64*196
    const int n = blockIdx.x;
    const bool isA = (blockIdx.y == 4);
    const int tid = threadIdx.x;
    const int co_l = tid / 12, oy = tid % 12;

    if (!isA) {
        const int co0 = blockIdx.y*64 + co_l;
        float acc[4][12];
#pragma unroll
        for (int q = 0; q < 4; q++)
#pragma unroll
            for (int i = 0; i < 12; i++) acc[q][i] = 0.f;

        for (int ci0 = 0; ci0 < 256; ci0 += 64) {
            __syncthreads();
            for (int idx = tid; idx < 64*196; idx += 192)
                sIn[idx] = in[((size_t)n*256 + ci0)*196 + idx];
            __syncthreads();

            for (int c = 0; c < 64; c++) {
                float w9[4][9];
#pragma unroll
                for (int q = 0; q < 4; q++) {
                    const float* wp = wp_ + ((size_t)(co0 + q*16)*256 + ci0 + c)*9;
#pragma unroll
                    for (int i = 0; i < 9; i++) w9[q][i] = wp[i];
                }
#pragma unroll
                for (int kh = 0; kh < 3; kh++) {
                    const float* row = sIn + (c*14 + oy + kh)*14;
                    float rv[14];
#pragma unroll
                    for (int i = 0; i < 14; i++) rv[i] = row[i];
#pragma unroll
                    for (int kw = 0; kw < 3; kw++) {
#pragma unroll
                        for (int q = 0; q < 4; q++) {
                            const float wv = w9[q][kh*3 + kw];
#pragma unroll
                            for (int ox = 0; ox < 12; ox++)
                                acc[q][ox] = fmaf(wv, rv[ox + kw], acc[q][ox]);
                        }
                    }
                }
            }
        }
#pragma unroll
        for (int q = 0; q < 4; q++) {
            const int co = co0 + q*16;
            const float sc = BN_SCALE * gp[co], bi = bp[co];
            float* op = outp + (((size_t)n*256 + co)*12 + oy)*12;
#pragma unroll
            for (int ox = 0; ox < 12; ox++)
                op[ox] = acc[q][ox]*sc + bi;
        }
    } else {
        const int co = co_l;
        float acc[12];
#pragma unroll
        for (int i = 0; i < 12; i++) acc[i] = 0.f;

        for (int ci0 = 0; ci0 < 256; ci0 += 64) {
            __syncthreads();
            for (int idx = tid; idx < 64*196; idx += 192)
                sIn[idx] = in[((size_t)n*256 + ci0)*196 + idx];
            __syncthreads();

            for (int c = 0; c < 64; c++) {
                const float* wp = wa_ + ((size_t)co*256 + ci0 + c)*9;
                float w9[9];
#pragma unroll
                for (int i = 0; i < 9; i++) w9[i] = wp[i];
#pragma unroll
                for (int kh = 0; kh < 3; kh++) {
                    const float* row = sIn + (c*14 + oy + kh)*14;
                    float rv[14];
#pragma unroll
                    for (int i = 0; i < 14; i++) rv[i] = row[i];
#pragma unroll
                    for (int kw = 0; kw < 3; kw++) {
                        const float wv = w9[kh*3 + kw];
#pragma unroll
                        for (int ox = 0; ox < 12; ox++)
                            acc[ox] = fmaf(wv, rv[ox + kw], acc[ox]);
                    }
                }
            }
        }
        const float sc = BN_SCALE * ga[co], bi = ba_[co];
        float* op = outa + (((size_t)n*16 + co)*12 + oy)*12;
#pragma unroll
        for (int ox = 0; ox < 12; ox++) {
            const float v = acc[ox]*sc + bi;
            op[ox] = 1.0f / (1.0f + __expf(-v));
        }
    }
}

// ---------------------------------------------------------------------------
// EM routing v13: slice-generic fused vote build (it=0 moments folded in for
// ALL layers, incl. BB=10), then 2 fused E+BC walks with UNR-way ILP.
// Vote passes per CTA: 3 always.
// ---------------------------------------------------------------------------
template<int NT, int A_, int BB, int KS, int STR, int PD, int IH, int OH,
         bool WPOSE, bool FC>
__global__ __launch_bounds__(NT, 1)
void em_kernel(const float* __restrict__ aIn,
               const float* __restrict__ poseIn,
               const float* __restrict__ Wm,    // (KS*KS*A_, BB, 4,4)
               const float* __restrict__ bu,
               const float* __restrict__ ba,
               const float* __restrict__ bng,
               const float* __restrict__ bnb,
               float* __restrict__ aOut,
               float* __restrict__ poseOut)
{
    constexpr int PS   = 16;
    constexpr int KK   = KS*KS;
    constexpr int KKA  = KK*A_;
    constexpr int BBPS = BB*PS;
    constexpr int VST  = BBPS + 4;
    constexpr int NV4  = BBPS/4;
    constexpr int NW   = NT/32;
    constexpr int KPW  = KKA/NW;
    static_assert(KPW*NW == KKA, "k split");
    constexpr int UNR  = (KPW % 4 == 0) ? 4 : 3;
    static_assert(KPW % UNR == 0, "unroll split");
    constexpr int NSL  = NT / NV4;            // build slices (8 or 12)
    static_assert(NSL <= NW, "slice slots");
    static_assert((NV4 % 4) == 0, "team alignment");
    constexpr int BTR  = (KKA + NSL - 1) / NSL;  // padded build trips

    extern __shared__ float sm[];
    float* sv   = sm;                    // KKA*VST
    float* pbm  = sv   + KKA*VST;        // NW*BBPS  (M1 partials)
    float* pbs  = pbm  + NW*BBPS;        // NW*BBPS  (M2 partials)
    float* smu  = pbs  + NW*BBPS;        // BBPS
    float* ssg  = smu  + BBPS;           // BBPS  1/(2 sigma)
    float* sa   = ssg  + BBPS;           // KKA
    float* spt  = sa   + KKA;            // KKA*PS
    float* pA   = spt  + KKA*PS;         // NW*17
    float* sao  = pA   + NW*17;          // BB
    float* sbia = sao  + BB;             // BB

    const int lidx = blockIdx.x;
    const int oy = lidx / OH, ox = lidx % OH;
    const int n  = blockIdx.y;
    const int tid  = threadIdx.x;
    const int wid  = tid >> 5;
    const int lane = tid & 31;
    const int j1   = lane >> 2;
    const bool act2 = (lane + 32 < NV4);
    const int j2   = (lane + 32) >> 2;

    // ---- Phase 0a: gather pose patch + a_in (zero-padded) ----
    for (int t = tid; t < KKA*PS; t += NT) {
        const int k = t / PS, p = t % PS;
        const int kk = k / A_, ai = k % A_;
        const int ki = kk / KS, kj = kk % KS;
        const int iy = oy*STR + ki - PD, ix = ox*STR + kj - PD;
        float v = 0.f;
        if (iy >= 0 && iy < IH && ix >= 0 && ix < IH)
            v = poseIn[(((size_t)n*A_*PS + ai*PS + p)*IH + iy)*IH + ix];
        spt[k*PS + p] = v;
    }
    for (int k = tid; k < KKA; k += NT) {
        const int kk = k / A_, ai = k % A_;
        const int ki = kk / KS, kj = kk % KS;
        const int iy = oy*STR + ki - PD, ix = ox*STR + kj - PD;
        float v = 0.f;
        if (iy >= 0 && iy < IH && ix >= 0 && ix < IH)
            v = aIn[(((size_t)n*A_ + ai)*IH + iy)*IH + ix];
        sa[k] = v;
    }
    __syncthreads();

    // ---- Finalize helper (runtime slice count ns, uniform-R flag) ----
    auto finalize = [&](float lam, int ns, bool uR) {
        if (wid < BB) {
            const int j = wid;
            float rv = 0.f;
            if (lane < ns) rv = pA[lane*17 + (uR ? 0 : j)];
#pragma unroll
            for (int d = 16; d; d >>= 1)
                rv += __shfl_xor_sync(0xffffffffu, rv, d);
            const float inv = 1.0f / (rv + EPSR);
            const float S = rv * inv;
            float lg = 0.f;
            if (lane < PS) {
                const int idx = j*PS + lane;
                float m = 0.f, s = 0.f;
                for (int h = 0; h < ns; h++) {
                    m += pbm[h*BBPS + idx];
                    s += pbs[h*BBPS + idx];
                }
                const float mu = m * inv;
                const float cv2 = s * inv;
                const float sg = fmaxf(cv2 - mu*mu*(2.0f - S), 0.0f) + EPSR;
                smu[idx] = mu;
                ssg[idx] = 0.5f / sg;
                lg = __logf(sg);
            }
            float sl = lg;
#pragma unroll
            for (int d = 16; d; d >>= 1)
                sl += __shfl_xor_sync(0xffffffffu, sl, d);
            if (lane == 0) {
                const float cost = ((float)PS*bu[j] + 0.5f*sl) * rv;
                const float ao = 1.0f / (1.0f + __expf(-lam*(ba[j] - cost)));
                sao[j]  = ao;
                sbia[j] = -0.5f*((float)PS*LOG2PI + sl) + __logf(ao + EPSR);
            }
        }
    };

    // ---- Phase 0b: fused vote build + it=0 moments (slice-generic) ----
    {
        const int s  = tid / NV4;        // slice index
        const int r4 = tid % NV4;        // fixed vote quad (team-aligned)
        const int jv = r4 >> 2;
        const int xi = lane & 3;
        const int base = lane & ~3;
        const bool on = (s < NSL);       // idle warps skip wholesale
        float4 m4 = make_float4(0,0,0,0), s4 = make_float4(0,0,0,0);
        float ra = 0.f;
        if (on) {
#pragma unroll
            for (int tr = 0; tr < BTR; tr++) {
                const int k = s + tr*NSL;
                const bool ok = (k < KKA);
                float4 p4 = make_float4(0,0,0,0), w4 = make_float4(0,0,0,0);
                if (ok) {
                    p4 = *(const float4*)(spt + k*PS + xi*4);
                    w4 = *(const float4*)(Wm + ((size_t)k*BB + jv)*16 + xi*4);
                }
                float4 acc; acc.x = acc.y = acc.z = acc.w = 0.f;
#pragma unroll
                for (int y = 0; y < 4; y++) {
                    const float py = (y==0) ? p4.x : (y==1) ? p4.y : (y==2) ? p4.z : p4.w;
                    float4 wy;
                    wy.x = __shfl_sync(0xffffffffu, w4.x, base + y);
                    wy.y = __shfl_sync(0xffffffffu, w4.y, base + y);
                    wy.z = __shfl_sync(0xffffffffu, w4.z, base + y);
                    wy.w = __shfl_sync(0xffffffffu, w4.w, base + y);
                    acc.x = fmaf(py, wy.x, acc.x);
                    acc.y = fmaf(py, wy.y, acc.y);
                    acc.z = fmaf(py, wy.z, acc.z);
                    acc.w = fmaf(py, wy.w, acc.w);
                }
                if (ok) {
                    *(float4*)(sv + k*VST + r4*4) = acc;
                    const float ak = sa[k] * (1.0f / (float)BB);
                    m4.x = fmaf(ak, acc.x, m4.x); s4.x = fmaf(ak, acc.x*acc.x, s4.x);
                    m4.y = fmaf(ak, acc.y, m4.y); s4.y = fmaf(ak, acc.y*acc.y, s4.y);
                    m4.z = fmaf(ak, acc.z, m4.z); s4.z = fmaf(ak, acc.z*acc.z, s4.z);
                    m4.w = fmaf(ak, acc.w, m4.w); s4.w = fmaf(ak, acc.w*acc.w, s4.w);
                    ra += ak;
                }
            }
            *(float4*)(pbm + s*BBPS + r4*4) = m4;
            *(float4*)(pbs + s*BBPS + r4*4) = s4;
            if (r4 == 0) pA[s*17] = ra;
        }
        __syncthreads();
        finalize(0.01f*(1.0f - 0.95f), NSL, true);
        __syncthreads();
    }

    // ---- Iteration walks (it = 1, 2) ----
    float p95 = 0.95f;
    for (int it = 1; it < 3; it++) {
        p95 *= 0.95f;
        const float lam = 0.01f * (1.0f - p95);

        float m_a[4], s_a[4], m_b[4], s_b[4];
#pragma unroll
        for (int q = 0; q < 4; q++) { m_a[q]=0.f; s_a[q]=0.f; m_b[q]=0.f; s_b[q]=0.f; }
        float r1 = 0.f, r2 = 0.f;

        float4 ma = *(const float4*)(smu + lane*4);
        float4 ga = *(const float4*)(ssg + lane*4);
        const float bia1 = sbia[j1];
        float4 mb = make_float4(0,0,0,0), gb = make_float4(0,0,0,0);
        float bia2 = 0.f;
        if (act2) {
            mb = *(const float4*)(smu + (lane+32)*4);
            gb = *(const float4*)(ssg + (lane+32)*4);
            bia2 = sbia[j2];
        }

#pragma unroll
        for (int kb = 0; kb < KPW; kb += UNR) {
            float4 va[UNR], vb[UNR];
            float  ak[UNR], ra1[UNR], ra2[UNR];
#pragma unroll
            for (int u = 0; u < UNR; u++) {
                const int k = wid + (kb + u)*NW;
                ak[u] = sa[k];
                const float* vk = sv + k*VST;
                va[u] = *(const float4*)(vk + lane*4);
                vb[u] = act2 ? *(const float4*)(vk + (lane+32)*4)
                             : make_float4(0,0,0,0);
            }
            float qa[UNR], qb[UNR];
#pragma unroll
            for (int u = 0; u < UNR; u++) {
                float d, q = 0.f;
                d = va[u].x-ma.x; q = fmaf(d*d, ga.x, q);
                d = va[u].y-ma.y; q = fmaf(d*d, ga.y, q);
                d = va[u].z-ma.z; q = fmaf(d*d, ga.z, q);
                d = va[u].w-ma.w; q = fmaf(d*d, ga.w, q);
                qa[u] = q;
                q = 0.f;
                if (act2) {
                    d = vb[u].x-mb.x; q = fmaf(d*d, gb.x, q);
                    d = vb[u].y-mb.y; q = fmaf(d*d, gb.y, q);
                    d = vb[u].z-mb.z; q = fmaf(d*d, gb.z, q);
                    d = vb[u].w-mb.w; q = fmaf(d*d, gb.w, q);
                }
                qb[u] = q;
            }
#pragma unroll
            for (int u = 0; u < UNR; u++) {
                qa[u] += __shfl_xor_sync(0xffffffffu, qa[u], 1);
                qb[u] += __shfl_xor_sync(0xffffffffu, qb[u], 1);
            }
#pragma unroll
            for (int u = 0; u < UNR; u++) {
                qa[u] += __shfl_xor_sync(0xffffffffu, qa[u], 2);
                qb[u] += __shfl_xor_sync(0xffffffffu, qb[u], 2);
            }
            float lnpa[UNR], lnpb[UNR], mx[UNR];
#pragma unroll
            for (int u = 0; u < UNR; u++) {
                lnpa[u] = bia1 - qa[u];
                lnpb[u] = act2 ? bia2 - qb[u] : -1e30f;
                mx[u] = fmaxf(lnpa[u], lnpb[u]);
            }
#pragma unroll
            for (int dd = 4; dd <= 16; dd <<= 1)
#pragma unroll
                for (int u = 0; u < UNR; u++)
                    mx[u] = fmaxf(mx[u], __shfl_xor_sync(0xffffffffu, mx[u], dd));
            float ea[UNR], eb[UNR], se[UNR];
#pragma unroll
            for (int u = 0; u < UNR; u++) {
                ea[u] = __expf(lnpa[u] - mx[u]);
                eb[u] = act2 ? __expf(lnpb[u] - mx[u]) : 0.f;
                se[u] = ea[u] + eb[u];
            }
#pragma unroll
            for (int dd = 4; dd <= 16; dd <<= 1)
#pragma unroll
                for (int u = 0; u < UNR; u++)
                    se[u] += __shfl_xor_sync(0xffffffffu, se[u], dd);
#pragma unroll
            for (int u = 0; u < UNR; u++) {
                const float sc = __fdividef(ak[u], se[u]);
                ra1[u] = ea[u] * sc;
                ra2[u] = eb[u] * sc;
            }
#pragma unroll
            for (int u = 0; u < UNR; u++) {
                m_a[0] = fmaf(ra1[u], va[u].x, m_a[0]); s_a[0] = fmaf(ra1[u], va[u].x*va[u].x, s_a[0]);
                m_a[1] = fmaf(ra1[u], va[u].y, m_a[1]); s_a[1] = fmaf(ra1[u], va[u].y*va[u].y, s_a[1]);
                m_a[2] = fmaf(ra1[u], va[u].z, m_a[2]); s_a[2] = fmaf(ra1[u], va[u].z*va[u].z, s_a[2]);
                m_a[3] = fmaf(ra1[u], va[u].w, m_a[3]); s_a[3] = fmaf(ra1[u], va[u].w*va[u].w, s_a[3]);
                r1 += ra1[u];
                if (act2) {
                    m_b[0] = fmaf(ra2[u], vb[u].x, m_b[0]); s_b[0] = fmaf(ra2[u], vb[u].x*vb[u].x, s_b[0]);
                    m_b[1] = fmaf(ra2[u], vb[u].y, m_b[1]); s_b[1] = fmaf(ra2[u], vb[u].y*vb[u].y, s_b[1]);
                    m_b[2] = fmaf(ra2[u], vb[u].z, m_b[2]); s_b[2] = fmaf(ra2[u], vb[u].z*vb[u].z, s_b[2]);
                    m_b[3] = fmaf(ra2[u], vb[u].w, m_b[3]); s_b[3] = fmaf(ra2[u], vb[u].w*vb[u].w, s_b[3]);
                    r2 += ra2[u];
                }
            }
        }
        *(float4*)(pbm + wid*BBPS + lane*4) = make_float4(m_a[0],m_a[1],m_a[2],m_a[3]);
        *(float4*)(pbs + wid*BBPS + lane*4) = make_float4(s_a[0],s_a[1],s_a[2],s_a[3]);
        if (act2) {
            *(float4*)(pbm + wid*BBPS + (lane+32)*4) = make_float4(m_b[0],m_b[1],m_b[2],m_b[3]);
            *(float4*)(pbs + wid*BBPS + (lane+32)*4) = make_float4(s_b[0],s_b[1],s_b[2],s_b[3]);
        }
        if ((lane & 3) == 0) {
            pA[wid*17 + j1] = r1;
            if (act2) pA[wid*17 + j2] = r2;
        }
        __syncthreads();
        finalize(lam, NW, false);
        __syncthreads();
    }

    // Outputs
    if (WPOSE) {
        for (int t = tid; t < BBPS; t += NT) {
            poseOut[(((size_t)n*BBPS + t)*OH + oy)*OH + ox] =
                smu[t]*BN_SCALE*bng[t] + bnb[t];
        }
    }
    if (tid < BB) {
        if (FC)
            aOut[((size_t)n*(OH*OH) + lidx)*BB + tid] = sao[tid];
        else
            aOut[(((size_t)n*BB + tid)*OH + oy)*OH + ox] = sao[tid];
    }
}

// ---------------------------------------------------------------------------
__global__ void reduce_kernel(const float* __restrict__ afc, float* __restrict__ out)
{
    const int t = blockIdx.x*blockDim.x + threadIdx.x;
    if (t < 320) {
        const int n = t / 10, j = t % 10;
        float s = 0.f;
        for (int l = 0; l < 25; l++) s += afc[(n*25 + l)*10 + j];
        out[t] = s * (1.0f/25.0f);
    }
}

// ---------------------------------------------------------------------------
extern "C" void kernel_launch(void* const* d_in, const int* in_sizes, int n_in,
                              void* d_out, int out_size)
{
    const float* x       = (const float*)d_in[0];
    const float* conv1_w = (const float*)d_in[1];
    const float* bn1_g   = (const float*)d_in[2];
    const float* bn1_b   = (const float*)d_in[3];
    const float* conva_w = (const float*)d_in[4];
    const float* bna_g   = (const float*)d_in[5];
    const float* bna_b   = (const float*)d_in[6];
    const float* convp_w = (const float*)d_in[7];
    const float* bnp_g   = (const float*)d_in[8];
    const float* bnp_b   = (const float*)d_in[9];
    const float* W1      = (const float*)d_in[10];
    const float* bu1     = (const float*)d_in[11];
    const float* ba1     = (const float*)d_in[12];
    const float* bnc1_g  = (const float*)d_in[13];
    const float* bnc1_b  = (const float*)d_in[14];
    const float* W2      = (const float*)d_in[15];
    const float* bu2     = (const float*)d_in[16];
    const float* ba2     = (const float*)d_in[17];
    const float* bnc2_g  = (const float*)d_in[18];
    const float* bnc2_b  = (const float*)d_in[19];
    const float* Wfc     = (const float*)d_in[20];
    const float* bufc    = (const float*)d_in[21];
    const float* bafc    = (const float*)d_in[22];

    float *buf1, *bufA, *bufP, *bufA2, *bufP2, *bufA3, *bufP3, *bufFC;
    cudaGetSymbolAddress((void**)&buf1,  g_buf1);
    cudaGetSymbolAddress((void**)&bufA,  g_bufA);
    cudaGetSymbolAddress((void**)&bufP,  g_bufP);
    cudaGetSymbolAddress((void**)&bufA2, g_bufA2);
    cudaGetSymbolAddress((void**)&bufP2, g_bufP2);
    cudaGetSymbolAddress((void**)&bufA3, g_bufA3);
    cudaGetSymbolAddress((void**)&bufP3, g_bufP3);
    cudaGetSymbolAddress((void**)&bufFC, g_bufFC);

    // conv1 + bn
    conv1_kernel<<<dim3(32,16), 224>>>(x, conv1_w, bn1_g, bn1_b, buf1);

    // conv3: convp tiles (y<4, NCO=4) + conva (y==4, sigmoid) in one launch
    const size_t c3smem = 64*196*sizeof(float);
    cudaFuncSetAttribute((const void*)conv3_both_kernel,
                         cudaFuncAttributeMaxDynamicSharedMemorySize, (int)c3smem);
    conv3_both_kernel<<<dim3(32,5), 192, c3smem>>>(
        buf1, convp_w, bnp_g, bnp_b, conva_w, bna_g, bna_b, bufP, bufA);

    constexpr int EMNT = 512, NW = EMNT/32;

    // smem floats: KKA*VST + 2*NW*BBPS + 2*BBPS + KKA + KKA*16 + NW*17 + 2*BB
    // EM1: 12x12 -> 6x6, k=3 s=2 p=1, A=16 B=16  (bnc1 fused)
    {
        constexpr int KKA = 144, BBPS = 256, VST = 260;
        const size_t sm1 = (size_t)(KKA*VST + 2*NW*BBPS + 2*BBPS
                                    + KKA + KKA*16 + NW*17 + 2*16) * sizeof(float);
        auto fn = em_kernel<EMNT,16,16,3,2,1,12,6,true,false>;
        cudaFuncSetAttribute(fn, cudaFuncAttributeMaxDynamicSharedMemorySize, (int)sm1);
        fn<<<dim3(36,32), EMNT, sm1>>>(bufA, bufP, W1, bu1, ba1, bnc1_g, bnc1_b, bufA2, bufP2);
    }

    // EM2: 6x6 -> 6x6, k=3 s=1 p=1, A=16 B=16  (bnc2 fused)
    {
        constexpr int KKA = 144, BBPS = 256, VST = 260;
        const size_t sm2 = (size_t)(KKA*VST + 2*NW*BBPS + 2*BBPS
                                    + KKA + KKA*16 + NW*17 + 2*16) * sizeof(float);
        auto fn = em_kernel<EMNT,16,16,3,1,1,6,6,true,false>;
        cudaFuncSetAttribute(fn, cudaFuncAttributeMaxDynamicSharedMemorySize, (int)sm2);
        fn<<<dim3(36,32), EMNT, sm2>>>(bufA2, bufP2, W2, bu2, ba2, bnc2_g, bnc2_b, bufA3, bufP3);
    }

    // EM3 (class caps): 6x6 -> 5x5, k=4 s=1 p=1, A=16 B=10, no pose out
    {
        constexpr int KKA = 256, BBPS = 160, VST = 164;
        const size_t sm3 = (size_t)(KKA*VST + 2*NW*BBPS + 2*BBPS
                                    + KKA + KKA*16 + NW*17 + 2*10) * sizeof(float);
        auto fn = em_kernel<EMNT,16,10,4,1,1,6,5,false,true>;
        cudaFuncSetAttribute(fn, cudaFuncAttributeMaxDynamicSharedMemorySize, (int)sm3);
        fn<<<dim3(25,32), EMNT, sm3>>>(bufA3, bufP3, Wfc, bufc, bafc, nullptr, nullptr, bufFC, nullptr);
    }

    // mean over spatial
    reduce_kernel<<<1, 320>>>(bufFC, (float*)d_out);
}

// round 14
// speedup vs baseline: 1.0783x; 1.0783x over previous
#include <cuda_runtime.h>
#include <math.h>
#include <stddef.h>

#define EPSR 1e-8f
// 1/sqrt(1 + 1e-5)
#define BN_SCALE 0.99999500003749969f
#define LOG2PI 1.8378770664093454836f

// ---------------------------------------------------------------------------
// Scratch buffers (device globals; no allocation allowed)
// ---------------------------------------------------------------------------
__device__ float g_buf1 [32*256*14*14];
__device__ float g_bufA [32*16*12*12];
__device__ float g_bufP [32*256*12*12];
__device__ float g_bufA2[32*16*6*6];
__device__ float g_bufP2[32*256*6*6];
__device__ float g_bufA3[32*16*6*6];
__device__ float g_bufP3[32*256*6*6];
__device__ float g_bufFC[32*25*10];

// ---------------------------------------------------------------------------
// conv1: x(32,3,32,32) * w(256,3,5,5) stride2 VALID -> (32,256,14,14), + bn
// ---------------------------------------------------------------------------
__global__ void conv1_kernel(const float* __restrict__ x,
                             const float* __restrict__ w,
                             const float* __restrict__ g,
                             const float* __restrict__ b,
                             float* __restrict__ out)
{
    __shared__ float sIn[3*32*33];
    const int n = blockIdx.x, cot = blockIdx.y;
    const int tid = threadIdx.x;

    for (int idx = tid; idx < 3*32*32; idx += 224) {
        int ci = idx >> 10, rem = idx & 1023, r = rem >> 5, c = rem & 31;
        sIn[(ci*32 + r)*33 + c] = x[n*3072 + idx];
    }
    __syncthreads();

    const int co_l = tid / 14, oy = tid % 14;
    const int co = cot*16 + co_l;

    float acc[14];
#pragma unroll
    for (int i = 0; i < 14; i++) acc[i] = 0.f;

    const float* wp = w + co*75;
#pragma unroll
    for (int ci = 0; ci < 3; ci++) {
#pragma unroll
        for (int kh = 0; kh < 5; kh++) {
            const float* row = sIn + (ci*32 + oy*2 + kh)*33;
#pragma unroll
            for (int kw = 0; kw < 5; kw++) {
                float wv = wp[(ci*5 + kh)*5 + kw];
#pragma unroll
                for (int ox = 0; ox < 14; ox++)
                    acc[ox] = fmaf(wv, row[ox*2 + kw], acc[ox]);
            }
        }
    }
    const float sc = BN_SCALE * g[co], bi = b[co];
    float* op = out + (((size_t)n*256 + co)*14 + oy)*14;
#pragma unroll
    for (int ox = 0; ox < 14; ox++) op[ox] = acc[ox]*sc + bi;
}

// ---------------------------------------------------------------------------
// conv3 combined (round-8/12 measured-good version): 3x3 conv -> 12x12 + bn.
//   blockIdx.y in [0,8): convp tile (NCO=2); blockIdx.y == 8: conva (sigmoid)
//   smem pitch 14 plain, scalar row loads, grid 32x9 (288 CTAs, 2 waves).
// ---------------------------------------------------------------------------
__global__ void conv3_both_kernel(const float* __restrict__ in,
                                  const float* __restrict__ wp_,
                                  const float* __restrict__ gp,
                                  const float* __restrict__ bp,
                                  const float* __restrict__ wa_,
                                  const float* __restrict__ ga,
                                  const float* __restrict__ ba_,
                                  float* __restrict__ outp,
                                  float* __restrict__ outa)
{
    extern __shared__ float sIn[];   // 64*196
    const int n = blockIdx.x;
    const bool isA = (blockIdx.y == 8);
    const int tid = threadIdx.x;
    const int co_l = tid / 12, oy = tid % 12;

    if (!isA) {
        const int co0 = blockIdx.y*32 + co_l;
        float acc[2][12];
#pragma unroll
        for (int q = 0; q < 2; q++)
#pragma unroll
            for (int i = 0; i < 12; i++) acc[q][i] = 0.f;

        for (int ci0 = 0; ci0 < 256; ci0 += 64) {
            __syncthreads();
            for (int idx = tid; idx < 64*196; idx += 192)
                sIn[idx] = in[((size_t)n*256 + ci0)*196 + idx];
            __syncthreads();

            for (int c = 0; c < 64; c++) {
                float w9[2][9];
#pragma unroll
                for (int q = 0; q < 2; q++) {
                    const float* wp = wp_ + ((size_t)(co0 + q*16)*256 + ci0 + c)*9;
#pragma unroll
                    for (int i = 0; i < 9; i++) w9[q][i] = wp[i];
                }
#pragma unroll
                for (int kh = 0; kh < 3; kh++) {
                    const float* row = sIn + (c*14 + oy + kh)*14;
                    float rv[14];
#pragma unroll
                    for (int i = 0; i < 14; i++) rv[i] = row[i];
#pragma unroll
                    for (int kw = 0; kw < 3; kw++) {
#pragma unroll
                        for (int q = 0; q < 2; q++) {
                            const float wv = w9[q][kh*3 + kw];
#pragma unroll
                            for (int ox = 0; ox < 12; ox++)
                                acc[q][ox] = fmaf(wv, rv[ox + kw], acc[q][ox]);
                        }
                    }
                }
            }
        }
#pragma unroll
        for (int q = 0; q < 2; q++) {
            const int co = co0 + q*16;
            const float sc = BN_SCALE * gp[co], bi = bp[co];
            float* op = outp + (((size_t)n*256 + co)*12 + oy)*12;
#pragma unroll
            for (int ox = 0; ox < 12; ox++)
                op[ox] = acc[q][ox]*sc + bi;
        }
    } else {
        const int co = co_l;
        float acc[12];
#pragma unroll
        for (int i = 0; i < 12; i++) acc[i] = 0.f;

        for (int ci0 = 0; ci0 < 256; ci0 += 64) {
            __syncthreads();
            for (int idx = tid; idx < 64*196; idx += 192)
                sIn[idx] = in[((size_t)n*256 + ci0)*196 + idx];
            __syncthreads();

            for (int c = 0; c < 64; c++) {
                const float* wp = wa_ + ((size_t)co*256 + ci0 + c)*9;
                float w9[9];
#pragma unroll
                for (int i = 0; i < 9; i++) w9[i] = wp[i];
#pragma unroll
                for (int kh = 0; kh < 3; kh++) {
                    const float* row = sIn + (c*14 + oy + kh)*14;
                    float rv[14];
#pragma unroll
                    for (int i = 0; i < 14; i++) rv[i] = row[i];
#pragma unroll
                    for (int kw = 0; kw < 3; kw++) {
                        const float wv = w9[kh*3 + kw];
#pragma unroll
                        for (int ox = 0; ox < 12; ox++)
                            acc[ox] = fmaf(wv, rv[ox + kw], acc[ox]);
                    }
                }
            }
        }
        const float sc = BN_SCALE * ga[co], bi = ba_[co];
        float* op = outa + (((size_t)n*16 + co)*12 + oy)*12;
#pragma unroll
        for (int ox = 0; ox < 12; ox++) {
            const float v = acc[ox]*sc + bi;
            op[ox] = 1.0f / (1.0f + __expf(-v));
        }
    }
}

// ---------------------------------------------------------------------------
// EM routing v13: slice-generic fused vote build (it=0 moments folded in for
// ALL layers, incl. BB=10), then 2 fused E+BC walks with UNR-way ILP.
// Vote passes per CTA: 3 always.
// ---------------------------------------------------------------------------
template<int NT, int A_, int BB, int KS, int STR, int PD, int IH, int OH,
         bool WPOSE, bool FC>
__global__ __launch_bounds__(NT, 1)
void em_kernel(const float* __restrict__ aIn,
               const float* __restrict__ poseIn,
               const float* __restrict__ Wm,    // (KS*KS*A_, BB, 4,4)
               const float* __restrict__ bu,
               const float* __restrict__ ba,
               const float* __restrict__ bng,
               const float* __restrict__ bnb,
               float* __restrict__ aOut,
               float* __restrict__ poseOut)
{
    constexpr int PS   = 16;
    constexpr int KK   = KS*KS;
    constexpr int KKA  = KK*A_;
    constexpr int BBPS = BB*PS;
    constexpr int VST  = BBPS + 4;
    constexpr int NV4  = BBPS/4;
    constexpr int NW   = NT/32;
    constexpr int KPW  = KKA/NW;
    static_assert(KPW*NW == KKA, "k split");
    constexpr int UNR  = (KPW % 4 == 0) ? 4 : 3;
    static_assert(KPW % UNR == 0, "unroll split");
    constexpr int NSL  = NT / NV4;            // build slices (8 or 12)
    static_assert(NSL <= NW, "slice slots");
    static_assert((NV4 % 4) == 0, "team alignment");
    constexpr int BTR  = (KKA + NSL - 1) / NSL;  // padded build trips

    extern __shared__ float sm[];
    float* sv   = sm;                    // KKA*VST
    float* pbm  = sv   + KKA*VST;        // NW*BBPS  (M1 partials)
    float* pbs  = pbm  + NW*BBPS;        // NW*BBPS  (M2 partials)
    float* smu  = pbs  + NW*BBPS;        // BBPS
    float* ssg  = smu  + BBPS;           // BBPS  1/(2 sigma)
    float* sa   = ssg  + BBPS;           // KKA
    float* spt  = sa   + KKA;            // KKA*PS
    float* pA   = spt  + KKA*PS;         // NW*17
    float* sao  = pA   + NW*17;          // BB
    float* sbia = sao  + BB;             // BB

    const int lidx = blockIdx.x;
    const int oy = lidx / OH, ox = lidx % OH;
    const int n  = blockIdx.y;
    const int tid  = threadIdx.x;
    const int wid  = tid >> 5;
    const int lane = tid & 31;
    const int j1   = lane >> 2;
    const bool act2 = (lane + 32 < NV4);
    const int j2   = (lane + 32) >> 2;

    // ---- Phase 0a: gather pose patch + a_in (zero-padded) ----
    for (int t = tid; t < KKA*PS; t += NT) {
        const int k = t / PS, p = t % PS;
        const int kk = k / A_, ai = k % A_;
        const int ki = kk / KS, kj = kk % KS;
        const int iy = oy*STR + ki - PD, ix = ox*STR + kj - PD;
        float v = 0.f;
        if (iy >= 0 && iy < IH && ix >= 0 && ix < IH)
            v = poseIn[(((size_t)n*A_*PS + ai*PS + p)*IH + iy)*IH + ix];
        spt[k*PS + p] = v;
    }
    for (int k = tid; k < KKA; k += NT) {
        const int kk = k / A_, ai = k % A_;
        const int ki = kk / KS, kj = kk % KS;
        const int iy = oy*STR + ki - PD, ix = ox*STR + kj - PD;
        float v = 0.f;
        if (iy >= 0 && iy < IH && ix >= 0 && ix < IH)
            v = aIn[(((size_t)n*A_ + ai)*IH + iy)*IH + ix];
        sa[k] = v;
    }
    __syncthreads();

    // ---- Finalize helper (runtime slice count ns, uniform-R flag) ----
    auto finalize = [&](float lam, int ns, bool uR) {
        if (wid < BB) {
            const int j = wid;
            float rv = 0.f;
            if (lane < ns) rv = pA[lane*17 + (uR ? 0 : j)];
#pragma unroll
            for (int d = 16; d; d >>= 1)
                rv += __shfl_xor_sync(0xffffffffu, rv, d);
            const float inv = 1.0f / (rv + EPSR);
            const float S = rv * inv;
            float lg = 0.f;
            if (lane < PS) {
                const int idx = j*PS + lane;
                float m = 0.f, s = 0.f;
                for (int h = 0; h < ns; h++) {
                    m += pbm[h*BBPS + idx];
                    s += pbs[h*BBPS + idx];
                }
                const float mu = m * inv;
                const float cv2 = s * inv;
                const float sg = fmaxf(cv2 - mu*mu*(2.0f - S), 0.0f) + EPSR;
                smu[idx] = mu;
                ssg[idx] = 0.5f / sg;
                lg = __logf(sg);
            }
            float sl = lg;
#pragma unroll
            for (int d = 16; d; d >>= 1)
                sl += __shfl_xor_sync(0xffffffffu, sl, d);
            if (lane == 0) {
                const float cost = ((float)PS*bu[j] + 0.5f*sl) * rv;
                const float ao = 1.0f / (1.0f + __expf(-lam*(ba[j] - cost)));
                sao[j]  = ao;
                sbia[j] = -0.5f*((float)PS*LOG2PI + sl) + __logf(ao + EPSR);
            }
        }
    };

    // ---- Phase 0b: fused vote build + it=0 moments (slice-generic) ----
    {
        const int s  = tid / NV4;        // slice index
        const int r4 = tid % NV4;        // fixed vote quad (team-aligned)
        const int jv = r4 >> 2;
        const int xi = lane & 3;
        const int base = lane & ~3;
        const bool on = (s < NSL);       // idle warps skip wholesale
        float4 m4 = make_float4(0,0,0,0), s4 = make_float4(0,0,0,0);
        float ra = 0.f;
        if (on) {
#pragma unroll
            for (int tr = 0; tr < BTR; tr++) {
                const int k = s + tr*NSL;
                const bool ok = (k < KKA);
                float4 p4 = make_float4(0,0,0,0), w4 = make_float4(0,0,0,0);
                if (ok) {
                    p4 = *(const float4*)(spt + k*PS + xi*4);
                    w4 = *(const float4*)(Wm + ((size_t)k*BB + jv)*16 + xi*4);
                }
                float4 acc; acc.x = acc.y = acc.z = acc.w = 0.f;
#pragma unroll
                for (int y = 0; y < 4; y++) {
                    const float py = (y==0) ? p4.x : (y==1) ? p4.y : (y==2) ? p4.z : p4.w;
                    float4 wy;
                    wy.x = __shfl_sync(0xffffffffu, w4.x, base + y);
                    wy.y = __shfl_sync(0xffffffffu, w4.y, base + y);
                    wy.z = __shfl_sync(0xffffffffu, w4.z, base + y);
                    wy.w = __shfl_sync(0xffffffffu, w4.w, base + y);
                    acc.x = fmaf(py, wy.x, acc.x);
                    acc.y = fmaf(py, wy.y, acc.y);
                    acc.z = fmaf(py, wy.z, acc.z);
                    acc.w = fmaf(py, wy.w, acc.w);
                }
                if (ok) {
                    *(float4*)(sv + k*VST + r4*4) = acc;
                    const float ak = sa[k] * (1.0f / (float)BB);
                    m4.x = fmaf(ak, acc.x, m4.x); s4.x = fmaf(ak, acc.x*acc.x, s4.x);
                    m4.y = fmaf(ak, acc.y, m4.y); s4.y = fmaf(ak, acc.y*acc.y, s4.y);
                    m4.z = fmaf(ak, acc.z, m4.z); s4.z = fmaf(ak, acc.z*acc.z, s4.z);
                    m4.w = fmaf(ak, acc.w, m4.w); s4.w = fmaf(ak, acc.w*acc.w, s4.w);
                    ra += ak;
                }
            }
            *(float4*)(pbm + s*BBPS + r4*4) = m4;
            *(float4*)(pbs + s*BBPS + r4*4) = s4;
            if (r4 == 0) pA[s*17] = ra;
        }
        __syncthreads();
        finalize(0.01f*(1.0f - 0.95f), NSL, true);
        __syncthreads();
    }

    // ---- Iteration walks (it = 1, 2) ----
    float p95 = 0.95f;
    for (int it = 1; it < 3; it++) {
        p95 *= 0.95f;
        const float lam = 0.01f * (1.0f - p95);

        float m_a[4], s_a[4], m_b[4], s_b[4];
#pragma unroll
        for (int q = 0; q < 4; q++) { m_a[q]=0.f; s_a[q]=0.f; m_b[q]=0.f; s_b[q]=0.f; }
        float r1 = 0.f, r2 = 0.f;

        float4 ma = *(const float4*)(smu + lane*4);
        float4 ga = *(const float4*)(ssg + lane*4);
        const float bia1 = sbia[j1];
        float4 mb = make_float4(0,0,0,0), gb = make_float4(0,0,0,0);
        float bia2 = 0.f;
        if (act2) {
            mb = *(const float4*)(smu + (lane+32)*4);
            gb = *(const float4*)(ssg + (lane+32)*4);
            bia2 = sbia[j2];
        }

#pragma unroll
        for (int kb = 0; kb < KPW; kb += UNR) {
            float4 va[UNR], vb[UNR];
            float  ak[UNR], ra1[UNR], ra2[UNR];
#pragma unroll
            for (int u = 0; u < UNR; u++) {
                const int k = wid + (kb + u)*NW;
                ak[u] = sa[k];
                const float* vk = sv + k*VST;
                va[u] = *(const float4*)(vk + lane*4);
                vb[u] = act2 ? *(const float4*)(vk + (lane+32)*4)
                             : make_float4(0,0,0,0);
            }
            float qa[UNR], qb[UNR];
#pragma unroll
            for (int u = 0; u < UNR; u++) {
                float d, q = 0.f;
                d = va[u].x-ma.x; q = fmaf(d*d, ga.x, q);
                d = va[u].y-ma.y; q = fmaf(d*d, ga.y, q);
                d = va[u].z-ma.z; q = fmaf(d*d, ga.z, q);
                d = va[u].w-ma.w; q = fmaf(d*d, ga.w, q);
                qa[u] = q;
                q = 0.f;
                if (act2) {
                    d = vb[u].x-mb.x; q = fmaf(d*d, gb.x, q);
                    d = vb[u].y-mb.y; q = fmaf(d*d, gb.y, q);
                    d = vb[u].z-mb.z; q = fmaf(d*d, gb.z, q);
                    d = vb[u].w-mb.w; q = fmaf(d*d, gb.w, q);
                }
                qb[u] = q;
            }
#pragma unroll
            for (int u = 0; u < UNR; u++) {
                qa[u] += __shfl_xor_sync(0xffffffffu, qa[u], 1);
                qb[u] += __shfl_xor_sync(0xffffffffu, qb[u], 1);
            }
#pragma unroll
            for (int u = 0; u < UNR; u++) {
                qa[u] += __shfl_xor_sync(0xffffffffu, qa[u], 2);
                qb[u] += __shfl_xor_sync(0xffffffffu, qb[u], 2);
            }
            float lnpa[UNR], lnpb[UNR], mx[UNR];
#pragma unroll
            for (int u = 0; u < UNR; u++) {
                lnpa[u] = bia1 - qa[u];
                lnpb[u] = act2 ? bia2 - qb[u] : -1e30f;
                mx[u] = fmaxf(lnpa[u], lnpb[u]);
            }
#pragma unroll
            for (int dd = 4; dd <= 16; dd <<= 1)
#pragma unroll
                for (int u = 0; u < UNR; u++)
                    mx[u] = fmaxf(mx[u], __shfl_xor_sync(0xffffffffu, mx[u], dd));
            float ea[UNR], eb[UNR], se[UNR];
#pragma unroll
            for (int u = 0; u < UNR; u++) {
                ea[u] = __expf(lnpa[u] - mx[u]);
                eb[u] = act2 ? __expf(lnpb[u] - mx[u]) : 0.f;
                se[u] = ea[u] + eb[u];
            }
#pragma unroll
            for (int dd = 4; dd <= 16; dd <<= 1)
#pragma unroll
                for (int u = 0; u < UNR; u++)
                    se[u] += __shfl_xor_sync(0xffffffffu, se[u], dd);
#pragma unroll
            for (int u = 0; u < UNR; u++) {
                const float sc = __fdividef(ak[u], se[u]);
                ra1[u] = ea[u] * sc;
                ra2[u] = eb[u] * sc;
            }
#pragma unroll
            for (int u = 0; u < UNR; u++) {
                m_a[0] = fmaf(ra1[u], va[u].x, m_a[0]); s_a[0] = fmaf(ra1[u], va[u].x*va[u].x, s_a[0]);
                m_a[1] = fmaf(ra1[u], va[u].y, m_a[1]); s_a[1] = fmaf(ra1[u], va[u].y*va[u].y, s_a[1]);
                m_a[2] = fmaf(ra1[u], va[u].z, m_a[2]); s_a[2] = fmaf(ra1[u], va[u].z*va[u].z, s_a[2]);
                m_a[3] = fmaf(ra1[u], va[u].w, m_a[3]); s_a[3] = fmaf(ra1[u], va[u].w*va[u].w, s_a[3]);
                r1 += ra1[u];
                if (act2) {
                    m_b[0] = fmaf(ra2[u], vb[u].x, m_b[0]); s_b[0] = fmaf(ra2[u], vb[u].x*vb[u].x, s_b[0]);
                    m_b[1] = fmaf(ra2[u], vb[u].y, m_b[1]); s_b[1] = fmaf(ra2[u], vb[u].y*vb[u].y, s_b[1]);
                    m_b[2] = fmaf(ra2[u], vb[u].z, m_b[2]); s_b[2] = fmaf(ra2[u], vb[u].z*vb[u].z, s_b[2]);
                    m_b[3] = fmaf(ra2[u], vb[u].w, m_b[3]); s_b[3] = fmaf(ra2[u], vb[u].w*vb[u].w, s_b[3]);
                    r2 += ra2[u];
                }
            }
        }
        *(float4*)(pbm + wid*BBPS + lane*4) = make_float4(m_a[0],m_a[1],m_a[2],m_a[3]);
        *(float4*)(pbs + wid*BBPS + lane*4) = make_float4(s_a[0],s_a[1],s_a[2],s_a[3]);
        if (act2) {
            *(float4*)(pbm + wid*BBPS + (lane+32)*4) = make_float4(m_b[0],m_b[1],m_b[2],m_b[3]);
            *(float4*)(pbs + wid*BBPS + (lane+32)*4) = make_float4(s_b[0],s_b[1],s_b[2],s_b[3]);
        }
        if ((lane & 3) == 0) {
            pA[wid*17 + j1] = r1;
            if (act2) pA[wid*17 + j2] = r2;
        }
        __syncthreads();
        finalize(lam, NW, false);
        __syncthreads();
    }

    // Outputs
    if (WPOSE) {
        for (int t = tid; t < BBPS; t += NT) {
            poseOut[(((size_t)n*BBPS + t)*OH + oy)*OH + ox] =
                smu[t]*BN_SCALE*bng[t] + bnb[t];
        }
    }
    if (tid < BB) {
        if (FC)
            aOut[((size_t)n*(OH*OH) + lidx)*BB + tid] = sao[tid];
        else
            aOut[(((size_t)n*BB + tid)*OH + oy)*OH + ox] = sao[tid];
    }
}

// ---------------------------------------------------------------------------
__global__ void reduce_kernel(const float* __restrict__ afc, float* __restrict__ out)
{
    const int t = blockIdx.x*blockDim.x + threadIdx.x;
    if (t < 320) {
        const int n = t / 10, j = t % 10;
        float s = 0.f;
        for (int l = 0; l < 25; l++) s += afc[(n*25 + l)*10 + j];
        out[t] = s * (1.0f/25.0f);
    }
}

// ---------------------------------------------------------------------------
extern "C" void kernel_launch(void* const* d_in, const int* in_sizes, int n_in,
                              void* d_out, int out_size)
{
    const float* x       = (const float*)d_in[0];
    const float* conv1_w = (const float*)d_in[1];
    const float* bn1_g   = (const float*)d_in[2];
    const float* bn1_b   = (const float*)d_in[3];
    const float* conva_w = (const float*)d_in[4];
    const float* bna_g   = (const float*)d_in[5];
    const float* bna_b   = (const float*)d_in[6];
    const float* convp_w = (const float*)d_in[7];
    const float* bnp_g   = (const float*)d_in[8];
    const float* bnp_b   = (const float*)d_in[9];
    const float* W1      = (const float*)d_in[10];
    const float* bu1     = (const float*)d_in[11];
    const float* ba1     = (const float*)d_in[12];
    const float* bnc1_g  = (const float*)d_in[13];
    const float* bnc1_b  = (const float*)d_in[14];
    const float* W2      = (const float*)d_in[15];
    const float* bu2     = (const float*)d_in[16];
    const float* ba2     = (const float*)d_in[17];
    const float* bnc2_g  = (const float*)d_in[18];
    const float* bnc2_b  = (const float*)d_in[19];
    const float* Wfc     = (const float*)d_in[20];
    const float* bufc    = (const float*)d_in[21];
    const float* bafc    = (const float*)d_in[22];

    float *buf1, *bufA, *bufP, *bufA2, *bufP2, *bufA3, *bufP3, *bufFC;
    cudaGetSymbolAddress((void**)&buf1,  g_buf1);
    cudaGetSymbolAddress((void**)&bufA,  g_bufA);
    cudaGetSymbolAddress((void**)&bufP,  g_bufP);
    cudaGetSymbolAddress((void**)&bufA2, g_bufA2);
    cudaGetSymbolAddress((void**)&bufP2, g_bufP2);
    cudaGetSymbolAddress((void**)&bufA3, g_bufA3);
    cudaGetSymbolAddress((void**)&bufP3, g_bufP3);
    cudaGetSymbolAddress((void**)&bufFC, g_bufFC);

    // conv1 + bn
    conv1_kernel<<<dim3(32,16), 224>>>(x, conv1_w, bn1_g, bn1_b, buf1);

    // conv3: convp tiles (y<8, NCO=2) + conva (y==8, sigmoid) in one launch
    const size_t c3smem = 64*196*sizeof(float);
    cudaFuncSetAttribute((const void*)conv3_both_kernel,
                         cudaFuncAttributeMaxDynamicSharedMemorySize, (int)c3smem);
    conv3_both_kernel<<<dim3(32,9), 192, c3smem>>>(
        buf1, convp_w, bnp_g, bnp_b, conva_w, bna_g, bna_b, bufP, bufA);

    constexpr int EMNT = 512, NW = EMNT/32;

    // smem floats: KKA*VST + 2*NW*BBPS + 2*BBPS + KKA + KKA*16 + NW*17 + 2*BB
    // EM1: 12x12 -> 6x6, k=3 s=2 p=1, A=16 B=16  (bnc1 fused)
    {
        constexpr int KKA = 144, BBPS = 256, VST = 260;
        const size_t sm1 = (size_t)(KKA*VST + 2*NW*BBPS + 2*BBPS
                                    + KKA + KKA*16 + NW*17 + 2*16) * sizeof(float);
        auto fn = em_kernel<EMNT,16,16,3,2,1,12,6,true,false>;
        cudaFuncSetAttribute(fn, cudaFuncAttributeMaxDynamicSharedMemorySize, (int)sm1);
        fn<<<dim3(36,32), EMNT, sm1>>>(bufA, bufP, W1, bu1, ba1, bnc1_g, bnc1_b, bufA2, bufP2);
    }

    // EM2: 6x6 -> 6x6, k=3 s=1 p=1, A=16 B=16  (bnc2 fused)
    {
        constexpr int KKA = 144, BBPS = 256, VST = 260;
        const size_t sm2 = (size_t)(KKA*VST + 2*NW*BBPS + 2*BBPS
                                    + KKA + KKA*16 + NW*17 + 2*16) * sizeof(float);
        auto fn = em_kernel<EMNT,16,16,3,1,1,6,6,true,false>;
        cudaFuncSetAttribute(fn, cudaFuncAttributeMaxDynamicSharedMemorySize, (int)sm2);
        fn<<<dim3(36,32), EMNT, sm2>>>(bufA2, bufP2, W2, bu2, ba2, bnc2_g, bnc2_b, bufA3, bufP3);
    }

    // EM3 (class caps): 6x6 -> 5x5, k=4 s=1 p=1, A=16 B=10, no pose out
    {
        constexpr int KKA = 256, BBPS = 160, VST = 164;
        const size_t sm3 = (size_t)(KKA*VST + 2*NW*BBPS + 2*BBPS
                                    + KKA + KKA*16 + NW*17 + 2*10) * sizeof(float);
        auto fn = em_kernel<EMNT,16,10,4,1,1,6,5,false,true>;
        cudaFuncSetAttribute(fn, cudaFuncAttributeMaxDynamicSharedMemorySize, (int)sm3);
        fn<<<dim3(25,32), EMNT, sm3>>>(bufA3, bufP3, Wfc, bufc, bafc, nullptr, nullptr, bufFC, nullptr);
    }

    // mean over spatial
    reduce_kernel<<<1, 320>>>(bufFC, (float*)d_out);
}

// round 15
// speedup vs baseline: 1.1096x; 1.0290x over previous
#include <cuda_runtime.h>
#include <math.h>
#include <stddef.h>

#define EPSR 1e-8f
// 1/sqrt(1 + 1e-5)
#define BN_SCALE 0.99999500003749969f
#define LOG2PI 1.8378770664093454836f

// ---------------------------------------------------------------------------
// Scratch buffers (device globals; no allocation allowed)
// ---------------------------------------------------------------------------
__device__ float g_buf1 [32*256*14*14];
__device__ float g_bufA [32*16*12*12];
__device__ float g_bufP [32*256*12*12];
__device__ float g_bufA2[32*16*6*6];
__device__ float g_bufP2[32*256*6*6];
__device__ float g_bufA3[32*16*6*6];
__device__ float g_bufP3[32*256*6*6];
__device__ float g_bufFC[32*25*10];

// ---------------------------------------------------------------------------
// conv1: x(32,3,32,32) * w(256,3,5,5) stride2 VALID -> (32,256,14,14), + bn
// ---------------------------------------------------------------------------
__global__ void conv1_kernel(const float* __restrict__ x,
                             const float* __restrict__ w,
                             const float* __restrict__ g,
                             const float* __restrict__ b,
                             float* __restrict__ out)
{
    __shared__ float sIn[3*32*33];
    const int n = blockIdx.x, cot = blockIdx.y;
    const int tid = threadIdx.x;

    for (int idx = tid; idx < 3*32*32; idx += 224) {
        int ci = idx >> 10, rem = idx & 1023, r = rem >> 5, c = rem & 31;
        sIn[(ci*32 + r)*33 + c] = x[n*3072 + idx];
    }
    __syncthreads();

    const int co_l = tid / 14, oy = tid % 14;
    const int co = cot*16 + co_l;

    float acc[14];
#pragma unroll
    for (int i = 0; i < 14; i++) acc[i] = 0.f;

    const float* wp = w + co*75;
#pragma unroll
    for (int ci = 0; ci < 3; ci++) {
#pragma unroll
        for (int kh = 0; kh < 5; kh++) {
            const float* row = sIn + (ci*32 + oy*2 + kh)*33;
#pragma unroll
            for (int kw = 0; kw < 5; kw++) {
                float wv = wp[(ci*5 + kh)*5 + kw];
#pragma unroll
                for (int ox = 0; ox < 14; ox++)
                    acc[ox] = fmaf(wv, row[ox*2 + kw], acc[ox]);
            }
        }
    }
    const float sc = BN_SCALE * g[co], bi = b[co];
    float* op = out + (((size_t)n*256 + co)*14 + oy)*14;
#pragma unroll
    for (int ox = 0; ox < 14; ox++) op[ox] = acc[ox]*sc + bi;
}

// ---------------------------------------------------------------------------
// conv3 combined (round-8/12 measured-good version): 3x3 conv -> 12x12 + bn.
//   blockIdx.y in [0,8): convp tile (NCO=2); blockIdx.y == 8: conva (sigmoid)
// ---------------------------------------------------------------------------
__global__ void conv3_both_kernel(const float* __restrict__ in,
                                  const float* __restrict__ wp_,
                                  const float* __restrict__ gp,
                                  const float* __restrict__ bp,
                                  const float* __restrict__ wa_,
                                  const float* __restrict__ ga,
                                  const float* __restrict__ ba_,
                                  float* __restrict__ outp,
                                  float* __restrict__ outa)
{
    extern __shared__ float sIn[];   // 64*196
    const int n = blockIdx.x;
    const bool isA = (blockIdx.y == 8);
    const int tid = threadIdx.x;
    const int co_l = tid / 12, oy = tid % 12;

    if (!isA) {
        const int co0 = blockIdx.y*32 + co_l;
        float acc[2][12];
#pragma unroll
        for (int q = 0; q < 2; q++)
#pragma unroll
            for (int i = 0; i < 12; i++) acc[q][i] = 0.f;

        for (int ci0 = 0; ci0 < 256; ci0 += 64) {
            __syncthreads();
            for (int idx = tid; idx < 64*196; idx += 192)
                sIn[idx] = in[((size_t)n*256 + ci0)*196 + idx];
            __syncthreads();

            for (int c = 0; c < 64; c++) {
                float w9[2][9];
#pragma unroll
                for (int q = 0; q < 2; q++) {
                    const float* wp = wp_ + ((size_t)(co0 + q*16)*256 + ci0 + c)*9;
#pragma unroll
                    for (int i = 0; i < 9; i++) w9[q][i] = wp[i];
                }
#pragma unroll
                for (int kh = 0; kh < 3; kh++) {
                    const float* row = sIn + (c*14 + oy + kh)*14;
                    float rv[14];
#pragma unroll
                    for (int i = 0; i < 14; i++) rv[i] = row[i];
#pragma unroll
                    for (int kw = 0; kw < 3; kw++) {
#pragma unroll
                        for (int q = 0; q < 2; q++) {
                            const float wv = w9[q][kh*3 + kw];
#pragma unroll
                            for (int ox = 0; ox < 12; ox++)
                                acc[q][ox] = fmaf(wv, rv[ox + kw], acc[q][ox]);
                        }
                    }
                }
            }
        }
#pragma unroll
        for (int q = 0; q < 2; q++) {
            const int co = co0 + q*16;
            const float sc = BN_SCALE * gp[co], bi = bp[co];
            float* op = outp + (((size_t)n*256 + co)*12 + oy)*12;
#pragma unroll
            for (int ox = 0; ox < 12; ox++)
                op[ox] = acc[q][ox]*sc + bi;
        }
    } else {
        const int co = co_l;
        float acc[12];
#pragma unroll
        for (int i = 0; i < 12; i++) acc[i] = 0.f;

        for (int ci0 = 0; ci0 < 256; ci0 += 64) {
            __syncthreads();
            for (int idx = tid; idx < 64*196; idx += 192)
                sIn[idx] = in[((size_t)n*256 + ci0)*196 + idx];
            __syncthreads();

            for (int c = 0; c < 64; c++) {
                const float* wp = wa_ + ((size_t)co*256 + ci0 + c)*9;
                float w9[9];
#pragma unroll
                for (int i = 0; i < 9; i++) w9[i] = wp[i];
#pragma unroll
                for (int kh = 0; kh < 3; kh++) {
                    const float* row = sIn + (c*14 + oy + kh)*14;
                    float rv[14];
#pragma unroll
                    for (int i = 0; i < 14; i++) rv[i] = row[i];
#pragma unroll
                    for (int kw = 0; kw < 3; kw++) {
                        const float wv = w9[kh*3 + kw];
#pragma unroll
                        for (int ox = 0; ox < 12; ox++)
                            acc[ox] = fmaf(wv, rv[ox + kw], acc[ox]);
                    }
                }
            }
        }
        const float sc = BN_SCALE * ga[co], bi = ba_[co];
        float* op = outa + (((size_t)n*16 + co)*12 + oy)*12;
#pragma unroll
        for (int ox = 0; ox < 12; ox++) {
            const float v = acc[ox]*sc + bi;
            op[ox] = 1.0f / (1.0f + __expf(-v));
        }
    }
}

// ---------------------------------------------------------------------------
// EM routing v15: build phase loads W[k][j] directly (4x LDG.128, no shuffle
// row-exchange) + it=0 moments fused; then 2 fused E+BC walks w/ UNR-way ILP.
// ---------------------------------------------------------------------------
template<int NT, int A_, int BB, int KS, int STR, int PD, int IH, int OH,
         bool WPOSE, bool FC>
__global__ __launch_bounds__(NT, 1)
void em_kernel(const float* __restrict__ aIn,
               const float* __restrict__ poseIn,
               const float* __restrict__ Wm,    // (KS*KS*A_, BB, 4,4)
               const float* __restrict__ bu,
               const float* __restrict__ ba,
               const float* __restrict__ bng,
               const float* __restrict__ bnb,
               float* __restrict__ aOut,
               float* __restrict__ poseOut)
{
    constexpr int PS   = 16;
    constexpr int KK   = KS*KS;
    constexpr int KKA  = KK*A_;
    constexpr int BBPS = BB*PS;
    constexpr int VST  = BBPS + 4;
    constexpr int NV4  = BBPS/4;
    constexpr int NW   = NT/32;
    constexpr int KPW  = KKA/NW;
    static_assert(KPW*NW == KKA, "k split");
    constexpr int UNR  = (KPW % 4 == 0) ? 4 : 3;
    static_assert(KPW % UNR == 0, "unroll split");
    constexpr int NSL  = NT / NV4;            // build slices (8 or 12)
    static_assert(NSL <= NW, "slice slots");
    static_assert((NV4 % 4) == 0, "team alignment");
    constexpr int BTR  = (KKA + NSL - 1) / NSL;  // padded build trips

    extern __shared__ float sm[];
    float* sv   = sm;                    // KKA*VST
    float* pbm  = sv   + KKA*VST;        // NW*BBPS  (M1 partials)
    float* pbs  = pbm  + NW*BBPS;        // NW*BBPS  (M2 partials)
    float* smu  = pbs  + NW*BBPS;        // BBPS
    float* ssg  = smu  + BBPS;           // BBPS  1/(2 sigma)
    float* sa   = ssg  + BBPS;           // KKA
    float* spt  = sa   + KKA;            // KKA*PS
    float* pA   = spt  + KKA*PS;         // NW*17
    float* sao  = pA   + NW*17;          // BB
    float* sbia = sao  + BB;             // BB

    const int lidx = blockIdx.x;
    const int oy = lidx / OH, ox = lidx % OH;
    const int n  = blockIdx.y;
    const int tid  = threadIdx.x;
    const int wid  = tid >> 5;
    const int lane = tid & 31;
    const int j1   = lane >> 2;
    const bool act2 = (lane + 32 < NV4);
    const int j2   = (lane + 32) >> 2;

    // ---- Phase 0a: gather pose patch + a_in (zero-padded) ----
    for (int t = tid; t < KKA*PS; t += NT) {
        const int k = t / PS, p = t % PS;
        const int kk = k / A_, ai = k % A_;
        const int ki = kk / KS, kj = kk % KS;
        const int iy = oy*STR + ki - PD, ix = ox*STR + kj - PD;
        float v = 0.f;
        if (iy >= 0 && iy < IH && ix >= 0 && ix < IH)
            v = poseIn[(((size_t)n*A_*PS + ai*PS + p)*IH + iy)*IH + ix];
        spt[k*PS + p] = v;
    }
    for (int k = tid; k < KKA; k += NT) {
        const int kk = k / A_, ai = k % A_;
        const int ki = kk / KS, kj = kk % KS;
        const int iy = oy*STR + ki - PD, ix = ox*STR + kj - PD;
        float v = 0.f;
        if (iy >= 0 && iy < IH && ix >= 0 && ix < IH)
            v = aIn[(((size_t)n*A_ + ai)*IH + iy)*IH + ix];
        sa[k] = v;
    }
    __syncthreads();

    // ---- Finalize helper (runtime slice count ns, uniform-R flag) ----
    auto finalize = [&](float lam, int ns, bool uR) {
        if (wid < BB) {
            const int j = wid;
            float rv = 0.f;
            if (lane < ns) rv = pA[lane*17 + (uR ? 0 : j)];
#pragma unroll
            for (int d = 16; d; d >>= 1)
                rv += __shfl_xor_sync(0xffffffffu, rv, d);
            const float inv = 1.0f / (rv + EPSR);
            const float S = rv * inv;
            float lg = 0.f;
            if (lane < PS) {
                const int idx = j*PS + lane;
                float m = 0.f, s = 0.f;
                for (int h = 0; h < ns; h++) {
                    m += pbm[h*BBPS + idx];
                    s += pbs[h*BBPS + idx];
                }
                const float mu = m * inv;
                const float cv2 = s * inv;
                const float sg = fmaxf(cv2 - mu*mu*(2.0f - S), 0.0f) + EPSR;
                smu[idx] = mu;
                ssg[idx] = 0.5f / sg;
                lg = __logf(sg);
            }
            float sl = lg;
#pragma unroll
            for (int d = 16; d; d >>= 1)
                sl += __shfl_xor_sync(0xffffffffu, sl, d);
            if (lane == 0) {
                const float cost = ((float)PS*bu[j] + 0.5f*sl) * rv;
                const float ao = 1.0f / (1.0f + __expf(-lam*(ba[j] - cost)));
                sao[j]  = ao;
                sbia[j] = -0.5f*((float)PS*LOG2PI + sl) + __logf(ao + EPSR);
            }
        }
    };

    // ---- Phase 0b: fused vote build + it=0 moments (direct W loads) ----
    {
        const int s  = tid / NV4;        // slice index
        const int r4 = tid % NV4;        // fixed vote quad
        const int jv = r4 >> 2;
        const int xi = r4 & 3;
        const bool on = (s < NSL);
        float4 m4 = make_float4(0,0,0,0), s4 = make_float4(0,0,0,0);
        float ra = 0.f;
        if (on) {
#pragma unroll
            for (int tr = 0; tr < BTR; tr++) {
                const int k = s + tr*NSL;
                if (k < KKA) {
                    const float4 p4 = *(const float4*)(spt + k*PS + xi*4);
                    const float* wj = Wm + ((size_t)k*BB + jv)*16;
                    const float4 w0 = *(const float4*)(wj);
                    const float4 w1 = *(const float4*)(wj + 4);
                    const float4 w2 = *(const float4*)(wj + 8);
                    const float4 w3 = *(const float4*)(wj + 12);
                    float4 acc;
                    acc.x = fmaf(p4.x,w0.x, fmaf(p4.y,w1.x, fmaf(p4.z,w2.x, p4.w*w3.x)));
                    acc.y = fmaf(p4.x,w0.y, fmaf(p4.y,w1.y, fmaf(p4.z,w2.y, p4.w*w3.y)));
                    acc.z = fmaf(p4.x,w0.z, fmaf(p4.y,w1.z, fmaf(p4.z,w2.z, p4.w*w3.z)));
                    acc.w = fmaf(p4.x,w0.w, fmaf(p4.y,w1.w, fmaf(p4.z,w2.w, p4.w*w3.w)));
                    *(float4*)(sv + k*VST + r4*4) = acc;
                    const float ak = sa[k] * (1.0f / (float)BB);
                    m4.x = fmaf(ak, acc.x, m4.x); s4.x = fmaf(ak, acc.x*acc.x, s4.x);
                    m4.y = fmaf(ak, acc.y, m4.y); s4.y = fmaf(ak, acc.y*acc.y, s4.y);
                    m4.z = fmaf(ak, acc.z, m4.z); s4.z = fmaf(ak, acc.z*acc.z, s4.z);
                    m4.w = fmaf(ak, acc.w, m4.w); s4.w = fmaf(ak, acc.w*acc.w, s4.w);
                    ra += ak;
                }
            }
            *(float4*)(pbm + s*BBPS + r4*4) = m4;
            *(float4*)(pbs + s*BBPS + r4*4) = s4;
            if (r4 == 0) pA[s*17] = ra;
        }
        __syncthreads();
        finalize(0.01f*(1.0f - 0.95f), NSL, true);
        __syncthreads();
    }

    // ---- Iteration walks (it = 1, 2) ----
    float p95 = 0.95f;
    for (int it = 1; it < 3; it++) {
        p95 *= 0.95f;
        const float lam = 0.01f * (1.0f - p95);

        float m_a[4], s_a[4], m_b[4], s_b[4];
#pragma unroll
        for (int q = 0; q < 4; q++) { m_a[q]=0.f; s_a[q]=0.f; m_b[q]=0.f; s_b[q]=0.f; }
        float r1 = 0.f, r2 = 0.f;

        float4 ma = *(const float4*)(smu + lane*4);
        float4 ga = *(const float4*)(ssg + lane*4);
        const float bia1 = sbia[j1];
        float4 mb = make_float4(0,0,0,0), gb = make_float4(0,0,0,0);
        float bia2 = 0.f;
        if (act2) {
            mb = *(const float4*)(smu + (lane+32)*4);
            gb = *(const float4*)(ssg + (lane+32)*4);
            bia2 = sbia[j2];
        }

#pragma unroll
        for (int kb = 0; kb < KPW; kb += UNR) {
            float4 va[UNR], vb[UNR];
            float  ak[UNR], ra1[UNR], ra2[UNR];
#pragma unroll
            for (int u = 0; u < UNR; u++) {
                const int k = wid + (kb + u)*NW;
                ak[u] = sa[k];
                const float* vk = sv + k*VST;
                va[u] = *(const float4*)(vk + lane*4);
                vb[u] = act2 ? *(const float4*)(vk + (lane+32)*4)
                             : make_float4(0,0,0,0);
            }
            float qa[UNR], qb[UNR];
#pragma unroll
            for (int u = 0; u < UNR; u++) {
                float d, q = 0.f;
                d = va[u].x-ma.x; q = fmaf(d*d, ga.x, q);
                d = va[u].y-ma.y; q = fmaf(d*d, ga.y, q);
                d = va[u].z-ma.z; q = fmaf(d*d, ga.z, q);
                d = va[u].w-ma.w; q = fmaf(d*d, ga.w, q);
                qa[u] = q;
                q = 0.f;
                if (act2) {
                    d = vb[u].x-mb.x; q = fmaf(d*d, gb.x, q);
                    d = vb[u].y-mb.y; q = fmaf(d*d, gb.y, q);
                    d = vb[u].z-mb.z; q = fmaf(d*d, gb.z, q);
                    d = vb[u].w-mb.w; q = fmaf(d*d, gb.w, q);
                }
                qb[u] = q;
            }
#pragma unroll
            for (int u = 0; u < UNR; u++) {
                qa[u] += __shfl_xor_sync(0xffffffffu, qa[u], 1);
                qb[u] += __shfl_xor_sync(0xffffffffu, qb[u], 1);
            }
#pragma unroll
            for (int u = 0; u < UNR; u++) {
                qa[u] += __shfl_xor_sync(0xffffffffu, qa[u], 2);
                qb[u] += __shfl_xor_sync(0xffffffffu, qb[u], 2);
            }
            float lnpa[UNR], lnpb[UNR], mx[UNR];
#pragma unroll
            for (int u = 0; u < UNR; u++) {
                lnpa[u] = bia1 - qa[u];
                lnpb[u] = act2 ? bia2 - qb[u] : -1e30f;
                mx[u] = fmaxf(lnpa[u], lnpb[u]);
            }
#pragma unroll
            for (int dd = 4; dd <= 16; dd <<= 1)
#pragma unroll
                for (int u = 0; u < UNR; u++)
                    mx[u] = fmaxf(mx[u], __shfl_xor_sync(0xffffffffu, mx[u], dd));
            float ea[UNR], eb[UNR], se[UNR];
#pragma unroll
            for (int u = 0; u < UNR; u++) {
                ea[u] = __expf(lnpa[u] - mx[u]);
                eb[u] = act2 ? __expf(lnpb[u] - mx[u]) : 0.f;
                se[u] = ea[u] + eb[u];
            }
#pragma unroll
            for (int dd = 4; dd <= 16; dd <<= 1)
#pragma unroll
                for (int u = 0; u < UNR; u++)
                    se[u] += __shfl_xor_sync(0xffffffffu, se[u], dd);
#pragma unroll
            for (int u = 0; u < UNR; u++) {
                const float sc = __fdividef(ak[u], se[u]);
                ra1[u] = ea[u] * sc;
                ra2[u] = eb[u] * sc;
            }
#pragma unroll
            for (int u = 0; u < UNR; u++) {
                m_a[0] = fmaf(ra1[u], va[u].x, m_a[0]); s_a[0] = fmaf(ra1[u], va[u].x*va[u].x, s_a[0]);
                m_a[1] = fmaf(ra1[u], va[u].y, m_a[1]); s_a[1] = fmaf(ra1[u], va[u].y*va[u].y, s_a[1]);
                m_a[2] = fmaf(ra1[u], va[u].z, m_a[2]); s_a[2] = fmaf(ra1[u], va[u].z*va[u].z, s_a[2]);
                m_a[3] = fmaf(ra1[u], va[u].w, m_a[3]); s_a[3] = fmaf(ra1[u], va[u].w*va[u].w, s_a[3]);
                r1 += ra1[u];
                if (act2) {
                    m_b[0] = fmaf(ra2[u], vb[u].x, m_b[0]); s_b[0] = fmaf(ra2[u], vb[u].x*vb[u].x, s_b[0]);
                    m_b[1] = fmaf(ra2[u], vb[u].y, m_b[1]); s_b[1] = fmaf(ra2[u], vb[u].y*vb[u].y, s_b[1]);
                    m_b[2] = fmaf(ra2[u], vb[u].z, m_b[2]); s_b[2] = fmaf(ra2[u], vb[u].z*vb[u].z, s_b[2]);
                    m_b[3] = fmaf(ra2[u], vb[u].w, m_b[3]); s_b[3] = fmaf(ra2[u], vb[u].w*vb[u].w, s_b[3]);
                    r2 += ra2[u];
                }
            }
        }
        *(float4*)(pbm + wid*BBPS + lane*4) = make_float4(m_a[0],m_a[1],m_a[2],m_a[3]);
        *(float4*)(pbs + wid*BBPS + lane*4) = make_float4(s_a[0],s_a[1],s_a[2],s_a[3]);
        if (act2) {
            *(float4*)(pbm + wid*BBPS + (lane+32)*4) = make_float4(m_b[0],m_b[1],m_b[2],m_b[3]);
            *(float4*)(pbs + wid*BBPS + (lane+32)*4) = make_float4(s_b[0],s_b[1],s_b[2],s_b[3]);
        }
        if ((lane & 3) == 0) {
            pA[wid*17 + j1] = r1;
            if (act2) pA[wid*17 + j2] = r2;
        }
        __syncthreads();
        finalize(lam, NW, false);
        __syncthreads();
    }

    // Outputs
    if (WPOSE) {
        for (int t = tid; t < BBPS; t += NT) {
            poseOut[(((size_t)n*BBPS + t)*OH + oy)*OH + ox] =
                smu[t]*BN_SCALE*bng[t] + bnb[t];
        }
    }
    if (tid < BB) {
        if (FC)
            aOut[((size_t)n*(OH*OH) + lidx)*BB + tid] = sao[tid];
        else
            aOut[(((size_t)n*BB + tid)*OH + oy)*OH + ox] = sao[tid];
    }
}

// ---------------------------------------------------------------------------
__global__ void reduce_kernel(const float* __restrict__ afc, float* __restrict__ out)
{
    const int t = blockIdx.x*blockDim.x + threadIdx.x;
    if (t < 320) {
        const int n = t / 10, j = t % 10;
        float s = 0.f;
        for (int l = 0; l < 25; l++) s += afc[(n*25 + l)*10 + j];
        out[t] = s * (1.0f/25.0f);
    }
}

// ---------------------------------------------------------------------------
extern "C" void kernel_launch(void* const* d_in, const int* in_sizes, int n_in,
                              void* d_out, int out_size)
{
    const float* x       = (const float*)d_in[0];
    const float* conv1_w = (const float*)d_in[1];
    const float* bn1_g   = (const float*)d_in[2];
    const float* bn1_b   = (const float*)d_in[3];
    const float* conva_w = (const float*)d_in[4];
    const float* bna_g   = (const float*)d_in[5];
    const float* bna_b   = (const float*)d_in[6];
    const float* convp_w = (const float*)d_in[7];
    const float* bnp_g   = (const float*)d_in[8];
    const float* bnp_b   = (const float*)d_in[9];
    const float* W1      = (const float*)d_in[10];
    const float* bu1     = (const float*)d_in[11];
    const float* ba1     = (const float*)d_in[12];
    const float* bnc1_g  = (const float*)d_in[13];
    const float* bnc1_b  = (const float*)d_in[14];
    const float* W2      = (const float*)d_in[15];
    const float* bu2     = (const float*)d_in[16];
    const float* ba2     = (const float*)d_in[17];
    const float* bnc2_g  = (const float*)d_in[18];
    const float* bnc2_b  = (const float*)d_in[19];
    const float* Wfc     = (const float*)d_in[20];
    const float* bufc    = (const float*)d_in[21];
    const float* bafc    = (const float*)d_in[22];

    float *buf1, *bufA, *bufP, *bufA2, *bufP2, *bufA3, *bufP3, *bufFC;
    cudaGetSymbolAddress((void**)&buf1,  g_buf1);
    cudaGetSymbolAddress((void**)&bufA,  g_bufA);
    cudaGetSymbolAddress((void**)&bufP,  g_bufP);
    cudaGetSymbolAddress((void**)&bufA2, g_bufA2);
    cudaGetSymbolAddress((void**)&bufP2, g_bufP2);
    cudaGetSymbolAddress((void**)&bufA3, g_bufA3);
    cudaGetSymbolAddress((void**)&bufP3, g_bufP3);
    cudaGetSymbolAddress((void**)&bufFC, g_bufFC);

    // conv1 + bn
    conv1_kernel<<<dim3(32,16), 224>>>(x, conv1_w, bn1_g, bn1_b, buf1);

    // conv3: convp tiles (y<8, NCO=2) + conva (y==8, sigmoid) in one launch
    const size_t c3smem = 64*196*sizeof(float);
    cudaFuncSetAttribute((const void*)conv3_both_kernel,
                         cudaFuncAttributeMaxDynamicSharedMemorySize, (int)c3smem);
    conv3_both_kernel<<<dim3(32,9), 192, c3smem>>>(
        buf1, convp_w, bnp_g, bnp_b, conva_w, bna_g, bna_b, bufP, bufA);

    constexpr int EMNT = 512, NW = EMNT/32;

    // smem floats: KKA*VST + 2*NW*BBPS + 2*BBPS + KKA + KKA*16 + NW*17 + 2*BB
    // EM1: 12x12 -> 6x6, k=3 s=2 p=1, A=16 B=16  (bnc1 fused)
    {
        constexpr int KKA = 144, BBPS = 256, VST = 260;
        const size_t sm1 = (size_t)(KKA*VST + 2*NW*BBPS + 2*BBPS
                                    + KKA + KKA*16 + NW*17 + 2*16) * sizeof(float);
        auto fn = em_kernel<EMNT,16,16,3,2,1,12,6,true,false>;
        cudaFuncSetAttribute(fn, cudaFuncAttributeMaxDynamicSharedMemorySize, (int)sm1);
        fn<<<dim3(36,32), EMNT, sm1>>>(bufA, bufP, W1, bu1, ba1, bnc1_g, bnc1_b, bufA2, bufP2);
    }

    // EM2: 6x6 -> 6x6, k=3 s=1 p=1, A=16 B=16  (bnc2 fused)
    {
        constexpr int KKA = 144, BBPS = 256, VST = 260;
        const size_t sm2 = (size_t)(KKA*VST + 2*NW*BBPS + 2*BBPS
                                    + KKA + KKA*16 + NW*17 + 2*16) * sizeof(float);
        auto fn = em_kernel<EMNT,16,16,3,1,1,6,6,true,false>;
        cudaFuncSetAttribute(fn, cudaFuncAttributeMaxDynamicSharedMemorySize, (int)sm2);
        fn<<<dim3(36,32), EMNT, sm2>>>(bufA2, bufP2, W2, bu2, ba2, bnc2_g, bnc2_b, bufA3, bufP3);
    }

    // EM3 (class caps): 6x6 -> 5x5, k=4 s=1 p=1, A=16 B=10, no pose out
    {
        constexpr int KKA = 256, BBPS = 160, VST = 164;
        const size_t sm3 = (size_t)(KKA*VST + 2*NW*BBPS + 2*BBPS
                                    + KKA + KKA*16 + NW*17 + 2*10) * sizeof(float);
        auto fn = em_kernel<EMNT,16,10,4,1,1,6,5,false,true>;
        cudaFuncSetAttribute(fn, cudaFuncAttributeMaxDynamicSharedMemorySize, (int)sm3);
        fn<<<dim3(25,32), EMNT, sm3>>>(bufA3, bufP3, Wfc, bufc, bafc, nullptr, nullptr, bufFC, nullptr);
    }

    // mean over spatial
    reduce_kernel<<<1, 320>>>(bufFC, (float*)d_out);
}

// round 16
// speedup vs baseline: 1.1323x; 1.0205x over previous
#include <cuda_runtime.h>
#include <math.h>
#include <stddef.h>

#define EPSR 1e-8f
// 1/sqrt(1 + 1e-5)
#define BN_SCALE 0.99999500003749969f
#define LOG2PI 1.8378770664093454836f

// ---------------------------------------------------------------------------
// Scratch buffers (device globals; no allocation allowed)
// ---------------------------------------------------------------------------
__device__ float g_buf1 [32*256*14*14];
__device__ float g_bufA [32*16*12*12];
__device__ float g_bufP [32*256*12*12];
__device__ float g_bufA2[32*16*6*6];
__device__ float g_bufP2[32*256*6*6];
__device__ float g_bufA3[32*16*6*6];
__device__ float g_bufP3[32*256*6*6];
__device__ float g_bufFC[32*25*10];

// ---------------------------------------------------------------------------
// conv1: x(32,3,32,32) * w(256,3,5,5) stride2 VALID -> (32,256,14,14), + bn
// ---------------------------------------------------------------------------
__global__ void conv1_kernel(const float* __restrict__ x,
                             const float* __restrict__ w,
                             const float* __restrict__ g,
                             const float* __restrict__ b,
                             float* __restrict__ out)
{
    __shared__ float sIn[3*32*33];
    const int n = blockIdx.x, cot = blockIdx.y;
    const int tid = threadIdx.x;

    for (int idx = tid; idx < 3*32*32; idx += 224) {
        int ci = idx >> 10, rem = idx & 1023, r = rem >> 5, c = rem & 31;
        sIn[(ci*32 + r)*33 + c] = x[n*3072 + idx];
    }
    __syncthreads();

    const int co_l = tid / 14, oy = tid % 14;
    const int co = cot*16 + co_l;

    float acc[14];
#pragma unroll
    for (int i = 0; i < 14; i++) acc[i] = 0.f;

    const float* wp = w + co*75;
#pragma unroll
    for (int ci = 0; ci < 3; ci++) {
#pragma unroll
        for (int kh = 0; kh < 5; kh++) {
            const float* row = sIn + (ci*32 + oy*2 + kh)*33;
#pragma unroll
            for (int kw = 0; kw < 5; kw++) {
                float wv = wp[(ci*5 + kh)*5 + kw];
#pragma unroll
                for (int ox = 0; ox < 14; ox++)
                    acc[ox] = fmaf(wv, row[ox*2 + kw], acc[ox]);
            }
        }
    }
    const float sc = BN_SCALE * g[co], bi = b[co];
    float* op = out + (((size_t)n*256 + co)*14 + oy)*14;
#pragma unroll
    for (int ox = 0; ox < 14; ox++) op[ox] = acc[ox]*sc + bi;
}

// ---------------------------------------------------------------------------
// conv3 combined v16: round-8 structure + double-buffered weight prefetch.
//   blockIdx.y in [0,8): convp tile (NCO=2); blockIdx.y == 8: conva (sigmoid)
// ---------------------------------------------------------------------------
__global__ void conv3_both_kernel(const float* __restrict__ in,
                                  const float* __restrict__ wp_,
                                  const float* __restrict__ gp,
                                  const float* __restrict__ bp,
                                  const float* __restrict__ wa_,
                                  const float* __restrict__ ga,
                                  const float* __restrict__ ba_,
                                  float* __restrict__ outp,
                                  float* __restrict__ outa)
{
    extern __shared__ float sIn[];   // 64*196
    const int n = blockIdx.x;
    const bool isA = (blockIdx.y == 8);
    const int tid = threadIdx.x;
    const int co_l = tid / 12, oy = tid % 12;

    if (!isA) {
        const int co0 = blockIdx.y*32 + co_l;
        float acc[2][12];
#pragma unroll
        for (int q = 0; q < 2; q++)
#pragma unroll
            for (int i = 0; i < 12; i++) acc[q][i] = 0.f;

        for (int ci0 = 0; ci0 < 256; ci0 += 64) {
            __syncthreads();
            for (int idx = tid; idx < 64*196; idx += 192)
                sIn[idx] = in[((size_t)n*256 + ci0)*196 + idx];
            __syncthreads();

            // double-buffered weight prefetch across the c loop
            float w9[2][2][9];
#pragma unroll
            for (int q = 0; q < 2; q++) {
                const float* wp = wp_ + ((size_t)(co0 + q*16)*256 + ci0)*9;
#pragma unroll
                for (int i = 0; i < 9; i++) w9[0][q][i] = __ldg(wp + i);
            }
#pragma unroll 2
            for (int c = 0; c < 64; c++) {
                const int cb = c & 1, nb = cb ^ 1;
                if (c + 1 < 64) {
#pragma unroll
                    for (int q = 0; q < 2; q++) {
                        const float* wp = wp_ + ((size_t)(co0 + q*16)*256 + ci0 + c + 1)*9;
#pragma unroll
                        for (int i = 0; i < 9; i++) w9[nb][q][i] = __ldg(wp + i);
                    }
                }
#pragma unroll
                for (int kh = 0; kh < 3; kh++) {
                    const float* row = sIn + (c*14 + oy + kh)*14;
                    float rv[14];
#pragma unroll
                    for (int i = 0; i < 14; i++) rv[i] = row[i];
#pragma unroll
                    for (int kw = 0; kw < 3; kw++) {
#pragma unroll
                        for (int q = 0; q < 2; q++) {
                            const float wv = w9[cb][q][kh*3 + kw];
#pragma unroll
                            for (int ox = 0; ox < 12; ox++)
                                acc[q][ox] = fmaf(wv, rv[ox + kw], acc[q][ox]);
                        }
                    }
                }
            }
        }
#pragma unroll
        for (int q = 0; q < 2; q++) {
            const int co = co0 + q*16;
            const float sc = BN_SCALE * gp[co], bi = bp[co];
            float* op = outp + (((size_t)n*256 + co)*12 + oy)*12;
#pragma unroll
            for (int ox = 0; ox < 12; ox++)
                op[ox] = acc[q][ox]*sc + bi;
        }
    } else {
        const int co = co_l;
        float acc[12];
#pragma unroll
        for (int i = 0; i < 12; i++) acc[i] = 0.f;

        for (int ci0 = 0; ci0 < 256; ci0 += 64) {
            __syncthreads();
            for (int idx = tid; idx < 64*196; idx += 192)
                sIn[idx] = in[((size_t)n*256 + ci0)*196 + idx];
            __syncthreads();

            float w9[2][9];
            {
                const float* wp = wa_ + ((size_t)co*256 + ci0)*9;
#pragma unroll
                for (int i = 0; i < 9; i++) w9[0][i] = __ldg(wp + i);
            }
#pragma unroll 2
            for (int c = 0; c < 64; c++) {
                const int cb = c & 1, nb = cb ^ 1;
                if (c + 1 < 64) {
                    const float* wp = wa_ + ((size_t)co*256 + ci0 + c + 1)*9;
#pragma unroll
                    for (int i = 0; i < 9; i++) w9[nb][i] = __ldg(wp + i);
                }
#pragma unroll
                for (int kh = 0; kh < 3; kh++) {
                    const float* row = sIn + (c*14 + oy + kh)*14;
                    float rv[14];
#pragma unroll
                    for (int i = 0; i < 14; i++) rv[i] = row[i];
#pragma unroll
                    for (int kw = 0; kw < 3; kw++) {
                        const float wv = w9[cb][kh*3 + kw];
#pragma unroll
                        for (int ox = 0; ox < 12; ox++)
                            acc[ox] = fmaf(wv, rv[ox + kw], acc[ox]);
                    }
                }
            }
        }
        const float sc = BN_SCALE * ga[co], bi = ba_[co];
        float* op = outa + (((size_t)n*16 + co)*12 + oy)*12;
#pragma unroll
        for (int ox = 0; ox < 12; ox++) {
            const float v = acc[ox]*sc + bi;
            op[ox] = 1.0f / (1.0f + __expf(-v));
        }
    }
}

// ---------------------------------------------------------------------------
// EM routing v15 (unchanged): direct-W vote build + fused it=0 moments,
// then 2 fused E+BC walks with UNR-way ILP.
// ---------------------------------------------------------------------------
template<int NT, int A_, int BB, int KS, int STR, int PD, int IH, int OH,
         bool WPOSE, bool FC>
__global__ __launch_bounds__(NT, 1)
void em_kernel(const float* __restrict__ aIn,
               const float* __restrict__ poseIn,
               const float* __restrict__ Wm,    // (KS*KS*A_, BB, 4,4)
               const float* __restrict__ bu,
               const float* __restrict__ ba,
               const float* __restrict__ bng,
               const float* __restrict__ bnb,
               float* __restrict__ aOut,
               float* __restrict__ poseOut)
{
    constexpr int PS   = 16;
    constexpr int KK   = KS*KS;
    constexpr int KKA  = KK*A_;
    constexpr int BBPS = BB*PS;
    constexpr int VST  = BBPS + 4;
    constexpr int NV4  = BBPS/4;
    constexpr int NW   = NT/32;
    constexpr int KPW  = KKA/NW;
    static_assert(KPW*NW == KKA, "k split");
    constexpr int UNR  = (KPW % 4 == 0) ? 4 : 3;
    static_assert(KPW % UNR == 0, "unroll split");
    constexpr int NSL  = NT / NV4;
    static_assert(NSL <= NW, "slice slots");
    static_assert((NV4 % 4) == 0, "team alignment");
    constexpr int BTR  = (KKA + NSL - 1) / NSL;

    extern __shared__ float sm[];
    float* sv   = sm;                    // KKA*VST
    float* pbm  = sv   + KKA*VST;        // NW*BBPS
    float* pbs  = pbm  + NW*BBPS;        // NW*BBPS
    float* smu  = pbs  + NW*BBPS;        // BBPS
    float* ssg  = smu  + BBPS;           // BBPS
    float* sa   = ssg  + BBPS;           // KKA
    float* spt  = sa   + KKA;            // KKA*PS
    float* pA   = spt  + KKA*PS;         // NW*17
    float* sao  = pA   + NW*17;          // BB
    float* sbia = sao  + BB;             // BB

    const int lidx = blockIdx.x;
    const int oy = lidx / OH, ox = lidx % OH;
    const int n  = blockIdx.y;
    const int tid  = threadIdx.x;
    const int wid  = tid >> 5;
    const int lane = tid & 31;
    const int j1   = lane >> 2;
    const bool act2 = (lane + 32 < NV4);
    const int j2   = (lane + 32) >> 2;

    // ---- Phase 0a: gather pose patch + a_in (zero-padded) ----
    for (int t = tid; t < KKA*PS; t += NT) {
        const int k = t / PS, p = t % PS;
        const int kk = k / A_, ai = k % A_;
        const int ki = kk / KS, kj = kk % KS;
        const int iy = oy*STR + ki - PD, ix = ox*STR + kj - PD;
        float v = 0.f;
        if (iy >= 0 && iy < IH && ix >= 0 && ix < IH)
            v = poseIn[(((size_t)n*A_*PS + ai*PS + p)*IH + iy)*IH + ix];
        spt[k*PS + p] = v;
    }
    for (int k = tid; k < KKA; k += NT) {
        const int kk = k / A_, ai = k % A_;
        const int ki = kk / KS, kj = kk % KS;
        const int iy = oy*STR + ki - PD, ix = ox*STR + kj - PD;
        float v = 0.f;
        if (iy >= 0 && iy < IH && ix >= 0 && ix < IH)
            v = aIn[(((size_t)n*A_ + ai)*IH + iy)*IH + ix];
        sa[k] = v;
    }
    __syncthreads();

    // ---- Finalize helper ----
    auto finalize = [&](float lam, int ns, bool uR) {
        if (wid < BB) {
            const int j = wid;
            float rv = 0.f;
            if (lane < ns) rv = pA[lane*17 + (uR ? 0 : j)];
#pragma unroll
            for (int d = 16; d; d >>= 1)
                rv += __shfl_xor_sync(0xffffffffu, rv, d);
            const float inv = 1.0f / (rv + EPSR);
            const float S = rv * inv;
            float lg = 0.f;
            if (lane < PS) {
                const int idx = j*PS + lane;
                float m = 0.f, s = 0.f;
                for (int h = 0; h < ns; h++) {
                    m += pbm[h*BBPS + idx];
                    s += pbs[h*BBPS + idx];
                }
                const float mu = m * inv;
                const float cv2 = s * inv;
                const float sg = fmaxf(cv2 - mu*mu*(2.0f - S), 0.0f) + EPSR;
                smu[idx] = mu;
                ssg[idx] = 0.5f / sg;
                lg = __logf(sg);
            }
            float sl = lg;
#pragma unroll
            for (int d = 16; d; d >>= 1)
                sl += __shfl_xor_sync(0xffffffffu, sl, d);
            if (lane == 0) {
                const float cost = ((float)PS*bu[j] + 0.5f*sl) * rv;
                const float ao = 1.0f / (1.0f + __expf(-lam*(ba[j] - cost)));
                sao[j]  = ao;
                sbia[j] = -0.5f*((float)PS*LOG2PI + sl) + __logf(ao + EPSR);
            }
        }
    };

    // ---- Phase 0b: fused vote build + it=0 moments (direct W loads) ----
    {
        const int s  = tid / NV4;
        const int r4 = tid % NV4;
        const int jv = r4 >> 2;
        const int xi = r4 & 3;
        const bool on = (s < NSL);
        float4 m4 = make_float4(0,0,0,0), s4 = make_float4(0,0,0,0);
        float ra = 0.f;
        if (on) {
#pragma unroll
            for (int tr = 0; tr < BTR; tr++) {
                const int k = s + tr*NSL;
                if (k < KKA) {
                    const float4 p4 = *(const float4*)(spt + k*PS + xi*4);
                    const float* wj = Wm + ((size_t)k*BB + jv)*16;
                    const float4 w0 = *(const float4*)(wj);
                    const float4 w1 = *(const float4*)(wj + 4);
                    const float4 w2 = *(const float4*)(wj + 8);
                    const float4 w3 = *(const float4*)(wj + 12);
                    float4 acc;
                    acc.x = fmaf(p4.x,w0.x, fmaf(p4.y,w1.x, fmaf(p4.z,w2.x, p4.w*w3.x)));
                    acc.y = fmaf(p4.x,w0.y, fmaf(p4.y,w1.y, fmaf(p4.z,w2.y, p4.w*w3.y)));
                    acc.z = fmaf(p4.x,w0.z, fmaf(p4.y,w1.z, fmaf(p4.z,w2.z, p4.w*w3.z)));
                    acc.w = fmaf(p4.x,w0.w, fmaf(p4.y,w1.w, fmaf(p4.z,w2.w, p4.w*w3.w)));
                    *(float4*)(sv + k*VST + r4*4) = acc;
                    const float ak = sa[k] * (1.0f / (float)BB);
                    m4.x = fmaf(ak, acc.x, m4.x); s4.x = fmaf(ak, acc.x*acc.x, s4.x);
                    m4.y = fmaf(ak, acc.y, m4.y); s4.y = fmaf(ak, acc.y*acc.y, s4.y);
                    m4.z = fmaf(ak, acc.z, m4.z); s4.z = fmaf(ak, acc.z*acc.z, s4.z);
                    m4.w = fmaf(ak, acc.w, m4.w); s4.w = fmaf(ak, acc.w*acc.w, s4.w);
                    ra += ak;
                }
            }
            *(float4*)(pbm + s*BBPS + r4*4) = m4;
            *(float4*)(pbs + s*BBPS + r4*4) = s4;
            if (r4 == 0) pA[s*17] = ra;
        }
        __syncthreads();
        finalize(0.01f*(1.0f - 0.95f), NSL, true);
        __syncthreads();
    }

    // ---- Iteration walks (it = 1, 2) ----
    float p95 = 0.95f;
    for (int it = 1; it < 3; it++) {
        p95 *= 0.95f;
        const float lam = 0.01f * (1.0f - p95);

        float m_a[4], s_a[4], m_b[4], s_b[4];
#pragma unroll
        for (int q = 0; q < 4; q++) { m_a[q]=0.f; s_a[q]=0.f; m_b[q]=0.f; s_b[q]=0.f; }
        float r1 = 0.f, r2 = 0.f;

        float4 ma = *(const float4*)(smu + lane*4);
        float4 ga = *(const float4*)(ssg + lane*4);
        const float bia1 = sbia[j1];
        float4 mb = make_float4(0,0,0,0), gb = make_float4(0,0,0,0);
        float bia2 = 0.f;
        if (act2) {
            mb = *(const float4*)(smu + (lane+32)*4);
            gb = *(const float4*)(ssg + (lane+32)*4);
            bia2 = sbia[j2];
        }

#pragma unroll
        for (int kb = 0; kb < KPW; kb += UNR) {
            float4 va[UNR], vb[UNR];
            float  ak[UNR], ra1[UNR], ra2[UNR];
#pragma unroll
            for (int u = 0; u < UNR; u++) {
                const int k = wid + (kb + u)*NW;
                ak[u] = sa[k];
                const float* vk = sv + k*VST;
                va[u] = *(const float4*)(vk + lane*4);
                vb[u] = act2 ? *(const float4*)(vk + (lane+32)*4)
                             : make_float4(0,0,0,0);
            }
            float qa[UNR], qb[UNR];
#pragma unroll
            for (int u = 0; u < UNR; u++) {
                float d, q = 0.f;
                d = va[u].x-ma.x; q = fmaf(d*d, ga.x, q);
                d = va[u].y-ma.y; q = fmaf(d*d, ga.y, q);
                d = va[u].z-ma.z; q = fmaf(d*d, ga.z, q);
                d = va[u].w-ma.w; q = fmaf(d*d, ga.w, q);
                qa[u] = q;
                q = 0.f;
                if (act2) {
                    d = vb[u].x-mb.x; q = fmaf(d*d, gb.x, q);
                    d = vb[u].y-mb.y; q = fmaf(d*d, gb.y, q);
                    d = vb[u].z-mb.z; q = fmaf(d*d, gb.z, q);
                    d = vb[u].w-mb.w; q = fmaf(d*d, gb.w, q);
                }
                qb[u] = q;
            }
#pragma unroll
            for (int u = 0; u < UNR; u++) {
                qa[u] += __shfl_xor_sync(0xffffffffu, qa[u], 1);
                qb[u] += __shfl_xor_sync(0xffffffffu, qb[u], 1);
            }
#pragma unroll
            for (int u = 0; u < UNR; u++) {
                qa[u] += __shfl_xor_sync(0xffffffffu, qa[u], 2);
                qb[u] += __shfl_xor_sync(0xffffffffu, qb[u], 2);
            }
            float lnpa[UNR], lnpb[UNR], mx[UNR];
#pragma unroll
            for (int u = 0; u < UNR; u++) {
                lnpa[u] = bia1 - qa[u];
                lnpb[u] = act2 ? bia2 - qb[u] : -1e30f;
                mx[u] = fmaxf(lnpa[u], lnpb[u]);
            }
#pragma unroll
            for (int dd = 4; dd <= 16; dd <<= 1)
#pragma unroll
                for (int u = 0; u < UNR; u++)
                    mx[u] = fmaxf(mx[u], __shfl_xor_sync(0xffffffffu, mx[u], dd));
            float ea[UNR], eb[UNR], se[UNR];
#pragma unroll
            for (int u = 0; u < UNR; u++) {
                ea[u] = __expf(lnpa[u] - mx[u]);
                eb[u] = act2 ? __expf(lnpb[u] - mx[u]) : 0.f;
                se[u] = ea[u] + eb[u];
            }
#pragma unroll
            for (int dd = 4; dd <= 16; dd <<= 1)
#pragma unroll
                for (int u = 0; u < UNR; u++)
                    se[u] += __shfl_xor_sync(0xffffffffu, se[u], dd);
#pragma unroll
            for (int u = 0; u < UNR; u++) {
                const float sc = __fdividef(ak[u], se[u]);
                ra1[u] = ea[u] * sc;
                ra2[u] = eb[u] * sc;
            }
#pragma unroll
            for (int u = 0; u < UNR; u++) {
                m_a[0] = fmaf(ra1[u], va[u].x, m_a[0]); s_a[0] = fmaf(ra1[u], va[u].x*va[u].x, s_a[0]);
                m_a[1] = fmaf(ra1[u], va[u].y, m_a[1]); s_a[1] = fmaf(ra1[u], va[u].y*va[u].y, s_a[1]);
                m_a[2] = fmaf(ra1[u], va[u].z, m_a[2]); s_a[2] = fmaf(ra1[u], va[u].z*va[u].z, s_a[2]);
                m_a[3] = fmaf(ra1[u], va[u].w, m_a[3]); s_a[3] = fmaf(ra1[u], va[u].w*va[u].w, s_a[3]);
                r1 += ra1[u];
                if (act2) {
                    m_b[0] = fmaf(ra2[u], vb[u].x, m_b[0]); s_b[0] = fmaf(ra2[u], vb[u].x*vb[u].x, s_b[0]);
                    m_b[1] = fmaf(ra2[u], vb[u].y, m_b[1]); s_b[1] = fmaf(ra2[u], vb[u].y*vb[u].y, s_b[1]);
                    m_b[2] = fmaf(ra2[u], vb[u].z, m_b[2]); s_b[2] = fmaf(ra2[u], vb[u].z*vb[u].z, s_b[2]);
                    m_b[3] = fmaf(ra2[u], vb[u].w, m_b[3]); s_b[3] = fmaf(ra2[u], vb[u].w*vb[u].w, s_b[3]);
                    r2 += ra2[u];
                }
            }
        }
        *(float4*)(pbm + wid*BBPS + lane*4) = make_float4(m_a[0],m_a[1],m_a[2],m_a[3]);
        *(float4*)(pbs + wid*BBPS + lane*4) = make_float4(s_a[0],s_a[1],s_a[2],s_a[3]);
        if (act2) {
            *(float4*)(pbm + wid*BBPS + (lane+32)*4) = make_float4(m_b[0],m_b[1],m_b[2],m_b[3]);
            *(float4*)(pbs + wid*BBPS + (lane+32)*4) = make_float4(s_b[0],s_b[1],s_b[2],s_b[3]);
        }
        if ((lane & 3) == 0) {
            pA[wid*17 + j1] = r1;
            if (act2) pA[wid*17 + j2] = r2;
        }
        __syncthreads();
        finalize(lam, NW, false);
        __syncthreads();
    }

    // Outputs
    if (WPOSE) {
        for (int t = tid; t < BBPS; t += NT) {
            poseOut[(((size_t)n*BBPS + t)*OH + oy)*OH + ox] =
                smu[t]*BN_SCALE*bng[t] + bnb[t];
        }
    }
    if (tid < BB) {
        if (FC)
            aOut[((size_t)n*(OH*OH) + lidx)*BB + tid] = sao[tid];
        else
            aOut[(((size_t)n*BB + tid)*OH + oy)*OH + ox] = sao[tid];
    }
}

// ---------------------------------------------------------------------------
__global__ void reduce_kernel(const float* __restrict__ afc, float* __restrict__ out)
{
    const int t = blockIdx.x*blockDim.x + threadIdx.x;
    if (t < 320) {
        const int n = t / 10, j = t % 10;
        float s = 0.f;
        for (int l = 0; l < 25; l++) s += afc[(n*25 + l)*10 + j];
        out[t] = s * (1.0f/25.0f);
    }
}

// ---------------------------------------------------------------------------
extern "C" void kernel_launch(void* const* d_in, const int* in_sizes, int n_in,
                              void* d_out, int out_size)
{
    const float* x       = (const float*)d_in[0];
    const float* conv1_w = (const float*)d_in[1];
    const float* bn1_g   = (const float*)d_in[2];
    const float* bn1_b   = (const float*)d_in[3];
    const float* conva_w = (const float*)d_in[4];
    const float* bna_g   = (const float*)d_in[5];
    const float* bna_b   = (const float*)d_in[6];
    const float* convp_w = (const float*)d_in[7];
    const float* bnp_g   = (const float*)d_in[8];
    const float* bnp_b   = (const float*)d_in[9];
    const float* W1      = (const float*)d_in[10];
    const float* bu1     = (const float*)d_in[11];
    const float* ba1     = (const float*)d_in[12];
    const float* bnc1_g  = (const float*)d_in[13];
    const float* bnc1_b  = (const float*)d_in[14];
    const float* W2      = (const float*)d_in[15];
    const float* bu2     = (const float*)d_in[16];
    const float* ba2     = (const float*)d_in[17];
    const float* bnc2_g  = (const float*)d_in[18];
    const float* bnc2_b  = (const float*)d_in[19];
    const float* Wfc     = (const float*)d_in[20];
    const float* bufc    = (const float*)d_in[21];
    const float* bafc    = (const float*)d_in[22];

    float *buf1, *bufA, *bufP, *bufA2, *bufP2, *bufA3, *bufP3, *bufFC;
    cudaGetSymbolAddress((void**)&buf1,  g_buf1);
    cudaGetSymbolAddress((void**)&bufA,  g_bufA);
    cudaGetSymbolAddress((void**)&bufP,  g_bufP);
    cudaGetSymbolAddress((void**)&bufA2, g_bufA2);
    cudaGetSymbolAddress((void**)&bufP2, g_bufP2);
    cudaGetSymbolAddress((void**)&bufA3, g_bufA3);
    cudaGetSymbolAddress((void**)&bufP3, g_bufP3);
    cudaGetSymbolAddress((void**)&bufFC, g_bufFC);

    // conv1 + bn
    conv1_kernel<<<dim3(32,16), 224>>>(x, conv1_w, bn1_g, bn1_b, buf1);

    // conv3: convp tiles (y<8, NCO=2) + conva (y==8, sigmoid) in one launch
    const size_t c3smem = 64*196*sizeof(float);
    cudaFuncSetAttribute((const void*)conv3_both_kernel,
                         cudaFuncAttributeMaxDynamicSharedMemorySize, (int)c3smem);
    conv3_both_kernel<<<dim3(32,9), 192, c3smem>>>(
        buf1, convp_w, bnp_g, bnp_b, conva_w, bna_g, bna_b, bufP, bufA);

    constexpr int EMNT = 512, NW = EMNT/32;

    // smem floats: KKA*VST + 2*NW*BBPS + 2*BBPS + KKA + KKA*16 + NW*17 + 2*BB
    // EM1: 12x12 -> 6x6, k=3 s=2 p=1, A=16 B=16  (bnc1 fused)
    {
        constexpr int KKA = 144, BBPS = 256, VST = 260;
        const size_t sm1 = (size_t)(KKA*VST + 2*NW*BBPS + 2*BBPS
                                    + KKA + KKA*16 + NW*17 + 2*16) * sizeof(float);
        auto fn = em_kernel<EMNT,16,16,3,2,1,12,6,true,false>;
        cudaFuncSetAttribute(fn, cudaFuncAttributeMaxDynamicSharedMemorySize, (int)sm1);
        fn<<<dim3(36,32), EMNT, sm1>>>(bufA, bufP, W1, bu1, ba1, bnc1_g, bnc1_b, bufA2, bufP2);
    }

    // EM2: 6x6 -> 6x6, k=3 s=1 p=1, A=16 B=16  (bnc2 fused)
    {
        constexpr int KKA = 144, BBPS = 256, VST = 260;
        const size_t sm2 = (size_t)(KKA*VST + 2*NW*BBPS + 2*BBPS
                                    + KKA + KKA*16 + NW*17 + 2*16) * sizeof(float);
        auto fn = em_kernel<EMNT,16,16,3,1,1,6,6,true,false>;
        cudaFuncSetAttribute(fn, cudaFuncAttributeMaxDynamicSharedMemorySize, (int)sm2);
        fn<<<dim3(36,32), EMNT, sm2>>>(bufA2, bufP2, W2, bu2, ba2, bnc2_g, bnc2_b, bufA3, bufP3);
    }

    // EM3 (class caps): 6x6 -> 5x5, k=4 s=1 p=1, A=16 B=10, no pose out
    {
        constexpr int KKA = 256, BBPS = 160, VST = 164;
        const size_t sm3 = (size_t)(KKA*VST + 2*NW*BBPS + 2*BBPS
                                    + KKA + KKA*16 + NW*17 + 2*10) * sizeof(float);
        auto fn = em_kernel<EMNT,16,10,4,1,1,6,5,false,true>;
        cudaFuncSetAttribute(fn, cudaFuncAttributeMaxDynamicSharedMemorySize, (int)sm3);
        fn<<<dim3(25,32), EMNT, sm3>>>(bufA3, bufP3, Wfc, bufc, bafc, nullptr, nullptr, bufFC, nullptr);
    }

    // mean over spatial
    reduce_kernel<<<1, 320>>>(bufFC, (float*)d_out);
}

// round 17
// speedup vs baseline: 1.1636x; 1.0277x over previous
#include <cuda_runtime.h>
#include <cuda_fp16.h>
#include <math.h>
#include <stddef.h>

#define EPSR 1e-8f
// 1/sqrt(1 + 1e-5)
#define BN_SCALE 0.99999500003749969f
#define LOG2PI 1.8378770664093454836f

// ---------------------------------------------------------------------------
// Scratch buffers (device globals; no allocation allowed)
// ---------------------------------------------------------------------------
__device__ float g_buf1 [32*256*14*14];
__device__ float g_bufA [32*16*12*12];
__device__ float g_bufP [32*256*12*12];
__device__ float g_bufA2[32*16*6*6];
__device__ float g_bufP2[32*256*6*6];
__device__ float g_bufA3[32*16*6*6];
__device__ float g_bufP3[32*256*6*6];
__device__ float g_bufFC[32*25*10];

// ---------------------------------------------------------------------------
// conv1: x(32,3,32,32) * w(256,3,5,5) stride2 VALID -> (32,256,14,14), + bn
// ---------------------------------------------------------------------------
__global__ void conv1_kernel(const float* __restrict__ x,
                             const float* __restrict__ w,
                             const float* __restrict__ g,
                             const float* __restrict__ b,
                             float* __restrict__ out)
{
    __shared__ float sIn[3*32*33];
    const int n = blockIdx.x, cot = blockIdx.y;
    const int tid = threadIdx.x;

    for (int idx = tid; idx < 3*32*32; idx += 224) {
        int ci = idx >> 10, rem = idx & 1023, r = rem >> 5, c = rem & 31;
        sIn[(ci*32 + r)*33 + c] = x[n*3072 + idx];
    }
    __syncthreads();

    const int co_l = tid / 14, oy = tid % 14;
    const int co = cot*16 + co_l;

    float acc[14];
#pragma unroll
    for (int i = 0; i < 14; i++) acc[i] = 0.f;

    const float* wp = w + co*75;
#pragma unroll
    for (int ci = 0; ci < 3; ci++) {
#pragma unroll
        for (int kh = 0; kh < 5; kh++) {
            const float* row = sIn + (ci*32 + oy*2 + kh)*33;
#pragma unroll
            for (int kw = 0; kw < 5; kw++) {
                float wv = wp[(ci*5 + kh)*5 + kw];
#pragma unroll
                for (int ox = 0; ox < 14; ox++)
                    acc[ox] = fmaf(wv, row[ox*2 + kw], acc[ox]);
            }
        }
    }
    const float sc = BN_SCALE * g[co], bi = b[co];
    float* op = out + (((size_t)n*256 + co)*14 + oy)*14;
#pragma unroll
    for (int ox = 0; ox < 14; ox++) op[ox] = acc[ox]*sc + bi;
}

// ---------------------------------------------------------------------------
// conv3 combined v16: round-8 structure + double-buffered weight prefetch.
// ---------------------------------------------------------------------------
__global__ void conv3_both_kernel(const float* __restrict__ in,
                                  const float* __restrict__ wp_,
                                  const float* __restrict__ gp,
                                  const float* __restrict__ bp,
                                  const float* __restrict__ wa_,
                                  const float* __restrict__ ga,
                                  const float* __restrict__ ba_,
                                  float* __restrict__ outp,
                                  float* __restrict__ outa)
{
    extern __shared__ float sIn[];   // 64*196
    const int n = blockIdx.x;
    const bool isA = (blockIdx.y == 8);
    const int tid = threadIdx.x;
    const int co_l = tid / 12, oy = tid % 12;

    if (!isA) {
        const int co0 = blockIdx.y*32 + co_l;
        float acc[2][12];
#pragma unroll
        for (int q = 0; q < 2; q++)
#pragma unroll
            for (int i = 0; i < 12; i++) acc[q][i] = 0.f;

        for (int ci0 = 0; ci0 < 256; ci0 += 64) {
            __syncthreads();
            for (int idx = tid; idx < 64*196; idx += 192)
                sIn[idx] = in[((size_t)n*256 + ci0)*196 + idx];
            __syncthreads();

            float w9[2][2][9];
#pragma unroll
            for (int q = 0; q < 2; q++) {
                const float* wp = wp_ + ((size_t)(co0 + q*16)*256 + ci0)*9;
#pragma unroll
                for (int i = 0; i < 9; i++) w9[0][q][i] = __ldg(wp + i);
            }
#pragma unroll 2
            for (int c = 0; c < 64; c++) {
                const int cb = c & 1, nb = cb ^ 1;
                if (c + 1 < 64) {
#pragma unroll
                    for (int q = 0; q < 2; q++) {
                        const float* wp = wp_ + ((size_t)(co0 + q*16)*256 + ci0 + c + 1)*9;
#pragma unroll
                        for (int i = 0; i < 9; i++) w9[nb][q][i] = __ldg(wp + i);
                    }
                }
#pragma unroll
                for (int kh = 0; kh < 3; kh++) {
                    const float* row = sIn + (c*14 + oy + kh)*14;
                    float rv[14];
#pragma unroll
                    for (int i = 0; i < 14; i++) rv[i] = row[i];
#pragma unroll
                    for (int kw = 0; kw < 3; kw++) {
#pragma unroll
                        for (int q = 0; q < 2; q++) {
                            const float wv = w9[cb][q][kh*3 + kw];
#pragma unroll
                            for (int ox = 0; ox < 12; ox++)
                                acc[q][ox] = fmaf(wv, rv[ox + kw], acc[q][ox]);
                        }
                    }
                }
            }
        }
#pragma unroll
        for (int q = 0; q < 2; q++) {
            const int co = co0 + q*16;
            const float sc = BN_SCALE * gp[co], bi = bp[co];
            float* op = outp + (((size_t)n*256 + co)*12 + oy)*12;
#pragma unroll
            for (int ox = 0; ox < 12; ox++)
                op[ox] = acc[q][ox]*sc + bi;
        }
    } else {
        const int co = co_l;
        float acc[12];
#pragma unroll
        for (int i = 0; i < 12; i++) acc[i] = 0.f;

        for (int ci0 = 0; ci0 < 256; ci0 += 64) {
            __syncthreads();
            for (int idx = tid; idx < 64*196; idx += 192)
                sIn[idx] = in[((size_t)n*256 + ci0)*196 + idx];
            __syncthreads();

            float w9[2][9];
            {
                const float* wp = wa_ + ((size_t)co*256 + ci0)*9;
#pragma unroll
                for (int i = 0; i < 9; i++) w9[0][i] = __ldg(wp + i);
            }
#pragma unroll 2
            for (int c = 0; c < 64; c++) {
                const int cb = c & 1, nb = cb ^ 1;
                if (c + 1 < 64) {
                    const float* wp = wa_ + ((size_t)co*256 + ci0 + c + 1)*9;
#pragma unroll
                    for (int i = 0; i < 9; i++) w9[nb][i] = __ldg(wp + i);
                }
#pragma unroll
                for (int kh = 0; kh < 3; kh++) {
                    const float* row = sIn + (c*14 + oy + kh)*14;
                    float rv[14];
#pragma unroll
                    for (int i = 0; i < 14; i++) rv[i] = row[i];
#pragma unroll
                    for (int kw = 0; kw < 3; kw++) {
                        const float wv = w9[cb][kh*3 + kw];
#pragma unroll
                        for (int ox = 0; ox < 12; ox++)
                            acc[ox] = fmaf(wv, rv[ox + kw], acc[ox]);
                    }
                }
            }
        }
        const float sc = BN_SCALE * ga[co], bi = ba_[co];
        float* op = outa + (((size_t)n*16 + co)*12 + oy)*12;
#pragma unroll
        for (int ox = 0; ox < 12; ox++) {
            const float v = acc[ox]*sc + bi;
            op[ox] = 1.0f / (1.0f + __expf(-v));
        }
    }
}

// ---------------------------------------------------------------------------
// fp16 vote pack/unpack helpers
// ---------------------------------------------------------------------------
__device__ __forceinline__ float4 ld_vote_h(const __half* base, int off) {
    uint2 raw = *(const uint2*)(base + off);
    __half2 h0 = *reinterpret_cast<__half2*>(&raw.x);
    __half2 h1 = *reinterpret_cast<__half2*>(&raw.y);
    const float2 f0 = __half22float2(h0), f1 = __half22float2(h1);
    return make_float4(f0.x, f0.y, f1.x, f1.y);
}
__device__ __forceinline__ float4 st_vote_h(__half* base, int off, float4 v) {
    __half2 h0 = __floats2half2_rn(v.x, v.y);
    __half2 h1 = __floats2half2_rn(v.z, v.w);
    uint2 raw;
    raw.x = *reinterpret_cast<unsigned*>(&h0);
    raw.y = *reinterpret_cast<unsigned*>(&h1);
    *(uint2*)(base + off) = raw;
    const float2 f0 = __half22float2(h0), f1 = __half22float2(h1);
    return make_float4(f0.x, f0.y, f1.x, f1.y);   // rounded values for moments
}

// ---------------------------------------------------------------------------
// EM routing v17: optional fp16 vote storage (HALFV) enabling 2 CTAs/SM at
// NT=256. Direct-W vote build + fused it=0 moments; 2 fused E+BC walks.
// ---------------------------------------------------------------------------
template<int NT, int MAXCTA, bool HALFV, int A_, int BB, int KS, int STR,
         int PD, int IH, int OH, bool WPOSE, bool FC>
__global__ __launch_bounds__(NT, MAXCTA)
void em_kernel(const float* __restrict__ aIn,
               const float* __restrict__ poseIn,
               const float* __restrict__ Wm,    // (KS*KS*A_, BB, 4,4)
               const float* __restrict__ bu,
               const float* __restrict__ ba,
               const float* __restrict__ bng,
               const float* __restrict__ bnb,
               float* __restrict__ aOut,
               float* __restrict__ poseOut)
{
    constexpr int PS   = 16;
    constexpr int KK   = KS*KS;
    constexpr int KKA  = KK*A_;
    constexpr int BBPS = BB*PS;
    constexpr int VST  = BBPS + 4;       // fp32 vote row stride
    constexpr int VSTH = BBPS + 8;       // fp16 vote row stride (8B aligned)
    constexpr int NV4  = BBPS/4;
    constexpr int NW   = NT/32;
    constexpr int KPW  = KKA/NW;
    static_assert(KPW*NW == KKA, "k split");
    constexpr int UNR  = (KPW % 4 == 0) ? 4 : 3;
    static_assert(KPW % UNR == 0, "unroll split");
    constexpr int NSL  = NT / NV4;
    static_assert(NSL >= 1 && NSL <= NW, "slice slots");
    static_assert((NV4 % 4) == 0, "team alignment");
    constexpr int BTR  = (KKA + NSL - 1) / NSL;
    constexpr int SVF  = HALFV ? (KKA*VSTH)/2 : KKA*VST;  // sv size in floats

    extern __shared__ float sm[];
    __half* svh = (__half*)sm;           // HALFV vote storage
    float*  svf = sm;                    // fp32 vote storage
    float* pbm  = sm  + SVF;             // NW*BBPS
    float* pbs  = pbm + NW*BBPS;         // NW*BBPS
    float* smu  = pbs + NW*BBPS;         // BBPS
    float* ssg  = smu + BBPS;            // BBPS
    float* sa   = ssg + BBPS;            // KKA
    float* spt  = sa  + KKA;             // KKA*PS
    float* pA   = spt + KKA*PS;          // NW*17
    float* sao  = pA  + NW*17;           // BB
    float* sbia = sao + BB;              // BB

    const int lidx = blockIdx.x;
    const int oy = lidx / OH, ox = lidx % OH;
    const int n  = blockIdx.y;
    const int tid  = threadIdx.x;
    const int wid  = tid >> 5;
    const int lane = tid & 31;
    const int j1   = lane >> 2;
    const bool act2 = (lane + 32 < NV4);
    const int j2   = (lane + 32) >> 2;

    // ---- Phase 0a: gather pose patch + a_in (zero-padded) ----
    for (int t = tid; t < KKA*PS; t += NT) {
        const int k = t / PS, p = t % PS;
        const int kk = k / A_, ai = k % A_;
        const int ki = kk / KS, kj = kk % KS;
        const int iy = oy*STR + ki - PD, ix = ox*STR + kj - PD;
        float v = 0.f;
        if (iy >= 0 && iy < IH && ix >= 0 && ix < IH)
            v = poseIn[(((size_t)n*A_*PS + ai*PS + p)*IH + iy)*IH + ix];
        spt[k*PS + p] = v;
    }
    for (int k = tid; k < KKA; k += NT) {
        const int kk = k / A_, ai = k % A_;
        const int ki = kk / KS, kj = kk % KS;
        const int iy = oy*STR + ki - PD, ix = ox*STR + kj - PD;
        float v = 0.f;
        if (iy >= 0 && iy < IH && ix >= 0 && ix < IH)
            v = aIn[(((size_t)n*A_ + ai)*IH + iy)*IH + ix];
        sa[k] = v;
    }
    __syncthreads();

    // ---- Finalize helper (ns slices; uniform-R flag; j strided by NW) ----
    auto finalize = [&](float lam, int ns, bool uR) {
        for (int j = wid; j < BB; j += NW) {
            float rv = 0.f;
            if (lane < ns) rv = pA[lane*17 + (uR ? 0 : j)];
#pragma unroll
            for (int d = 16; d; d >>= 1)
                rv += __shfl_xor_sync(0xffffffffu, rv, d);
            const float inv = 1.0f / (rv + EPSR);
            const float S = rv * inv;
            float lg = 0.f;
            if (lane < PS) {
                const int idx = j*PS + lane;
                float m = 0.f, s = 0.f;
                for (int h = 0; h < ns; h++) {
                    m += pbm[h*BBPS + idx];
                    s += pbs[h*BBPS + idx];
                }
                const float mu = m * inv;
                const float cv2 = s * inv;
                const float sg = fmaxf(cv2 - mu*mu*(2.0f - S), 0.0f) + EPSR;
                smu[idx] = mu;
                ssg[idx] = 0.5f / sg;
                lg = __logf(sg);
            }
            float sl = lg;
#pragma unroll
            for (int d = 16; d; d >>= 1)
                sl += __shfl_xor_sync(0xffffffffu, sl, d);
            if (lane == 0) {
                const float cost = ((float)PS*bu[j] + 0.5f*sl) * rv;
                const float ao = 1.0f / (1.0f + __expf(-lam*(ba[j] - cost)));
                sao[j]  = ao;
                sbia[j] = -0.5f*((float)PS*LOG2PI + sl) + __logf(ao + EPSR);
            }
        }
    };

    // ---- Phase 0b: fused vote build + it=0 moments (direct W loads) ----
    {
        const int s  = tid / NV4;
        const int r4 = tid % NV4;
        const int jv = r4 >> 2;
        const int xi = r4 & 3;
        const bool on = (s < NSL);
        float4 m4 = make_float4(0,0,0,0), s4 = make_float4(0,0,0,0);
        float ra = 0.f;
        if (on) {
#pragma unroll
            for (int tr = 0; tr < BTR; tr++) {
                const int k = s + tr*NSL;
                if (k < KKA) {
                    const float4 p4 = *(const float4*)(spt + k*PS + xi*4);
                    const float* wj = Wm + ((size_t)k*BB + jv)*16;
                    const float4 w0 = *(const float4*)(wj);
                    const float4 w1 = *(const float4*)(wj + 4);
                    const float4 w2 = *(const float4*)(wj + 8);
                    const float4 w3 = *(const float4*)(wj + 12);
                    float4 acc;
                    acc.x = fmaf(p4.x,w0.x, fmaf(p4.y,w1.x, fmaf(p4.z,w2.x, p4.w*w3.x)));
                    acc.y = fmaf(p4.x,w0.y, fmaf(p4.y,w1.y, fmaf(p4.z,w2.y, p4.w*w3.y)));
                    acc.z = fmaf(p4.x,w0.z, fmaf(p4.y,w1.z, fmaf(p4.z,w2.z, p4.w*w3.z)));
                    acc.w = fmaf(p4.x,w0.w, fmaf(p4.y,w1.w, fmaf(p4.z,w2.w, p4.w*w3.w)));
                    if (HALFV)
                        acc = st_vote_h(svh, k*VSTH + r4*4, acc);  // rounded
                    else
                        *(float4*)(svf + k*VST + r4*4) = acc;
                    const float ak = sa[k] * (1.0f / (float)BB);
                    m4.x = fmaf(ak, acc.x, m4.x); s4.x = fmaf(ak, acc.x*acc.x, s4.x);
                    m4.y = fmaf(ak, acc.y, m4.y); s4.y = fmaf(ak, acc.y*acc.y, s4.y);
                    m4.z = fmaf(ak, acc.z, m4.z); s4.z = fmaf(ak, acc.z*acc.z, s4.z);
                    m4.w = fmaf(ak, acc.w, m4.w); s4.w = fmaf(ak, acc.w*acc.w, s4.w);
                    ra += ak;
                }
            }
            *(float4*)(pbm + s*BBPS + r4*4) = m4;
            *(float4*)(pbs + s*BBPS + r4*4) = s4;
            if (r4 == 0) pA[s*17] = ra;
        }
        __syncthreads();
        finalize(0.01f*(1.0f - 0.95f), NSL, true);
        __syncthreads();
    }

    // ---- Iteration walks (it = 1, 2) ----
    float p95 = 0.95f;
    for (int it = 1; it < 3; it++) {
        p95 *= 0.95f;
        const float lam = 0.01f * (1.0f - p95);

        float m_a[4], s_a[4], m_b[4], s_b[4];
#pragma unroll
        for (int q = 0; q < 4; q++) { m_a[q]=0.f; s_a[q]=0.f; m_b[q]=0.f; s_b[q]=0.f; }
        float r1 = 0.f, r2 = 0.f;

        float4 ma = *(const float4*)(smu + lane*4);
        float4 ga = *(const float4*)(ssg + lane*4);
        const float bia1 = sbia[j1];
        float4 mb = make_float4(0,0,0,0), gb = make_float4(0,0,0,0);
        float bia2 = 0.f;
        if (act2) {
            mb = *(const float4*)(smu + (lane+32)*4);
            gb = *(const float4*)(ssg + (lane+32)*4);
            bia2 = sbia[j2];
        }

#pragma unroll
        for (int kb = 0; kb < KPW; kb += UNR) {
            float4 va[UNR], vb[UNR];
            float  ak[UNR], ra1[UNR], ra2[UNR];
#pragma unroll
            for (int u = 0; u < UNR; u++) {
                const int k = wid + (kb + u)*NW;
                ak[u] = sa[k];
                if (HALFV) {
                    va[u] = ld_vote_h(svh, k*VSTH + lane*4);
                    vb[u] = act2 ? ld_vote_h(svh, k*VSTH + (lane+32)*4)
                                 : make_float4(0,0,0,0);
                } else {
                    const float* vk = svf + k*VST;
                    va[u] = *(const float4*)(vk + lane*4);
                    vb[u] = act2 ? *(const float4*)(vk + (lane+32)*4)
                                 : make_float4(0,0,0,0);
                }
            }
            float qa[UNR], qb[UNR];
#pragma unroll
            for (int u = 0; u < UNR; u++) {
                float d, q = 0.f;
                d = va[u].x-ma.x; q = fmaf(d*d, ga.x, q);
                d = va[u].y-ma.y; q = fmaf(d*d, ga.y, q);
                d = va[u].z-ma.z; q = fmaf(d*d, ga.z, q);
                d = va[u].w-ma.w; q = fmaf(d*d, ga.w, q);
                qa[u] = q;
                q = 0.f;
                if (act2) {
                    d = vb[u].x-mb.x; q = fmaf(d*d, gb.x, q);
                    d = vb[u].y-mb.y; q = fmaf(d*d, gb.y, q);
                    d = vb[u].z-mb.z; q = fmaf(d*d, gb.z, q);
                    d = vb[u].w-mb.w; q = fmaf(d*d, gb.w, q);
                }
                qb[u] = q;
            }
#pragma unroll
            for (int u = 0; u < UNR; u++) {
                qa[u] += __shfl_xor_sync(0xffffffffu, qa[u], 1);
                qb[u] += __shfl_xor_sync(0xffffffffu, qb[u], 1);
            }
#pragma unroll
            for (int u = 0; u < UNR; u++) {
                qa[u] += __shfl_xor_sync(0xffffffffu, qa[u], 2);
                qb[u] += __shfl_xor_sync(0xffffffffu, qb[u], 2);
            }
            float lnpa[UNR], lnpb[UNR], mx[UNR];
#pragma unroll
            for (int u = 0; u < UNR; u++) {
                lnpa[u] = bia1 - qa[u];
                lnpb[u] = act2 ? bia2 - qb[u] : -1e30f;
                mx[u] = fmaxf(lnpa[u], lnpb[u]);
            }
#pragma unroll
            for (int dd = 4; dd <= 16; dd <<= 1)
#pragma unroll
                for (int u = 0; u < UNR; u++)
                    mx[u] = fmaxf(mx[u], __shfl_xor_sync(0xffffffffu, mx[u], dd));
            float ea[UNR], eb[UNR], se[UNR];
#pragma unroll
            for (int u = 0; u < UNR; u++) {
                ea[u] = __expf(lnpa[u] - mx[u]);
                eb[u] = act2 ? __expf(lnpb[u] - mx[u]) : 0.f;
                se[u] = ea[u] + eb[u];
            }
#pragma unroll
            for (int dd = 4; dd <= 16; dd <<= 1)
#pragma unroll
                for (int u = 0; u < UNR; u++)
                    se[u] += __shfl_xor_sync(0xffffffffu, se[u], dd);
#pragma unroll
            for (int u = 0; u < UNR; u++) {
                const float sc = __fdividef(ak[u], se[u]);
                ra1[u] = ea[u] * sc;
                ra2[u] = eb[u] * sc;
            }
#pragma unroll
            for (int u = 0; u < UNR; u++) {
                m_a[0] = fmaf(ra1[u], va[u].x, m_a[0]); s_a[0] = fmaf(ra1[u], va[u].x*va[u].x, s_a[0]);
                m_a[1] = fmaf(ra1[u], va[u].y, m_a[1]); s_a[1] = fmaf(ra1[u], va[u].y*va[u].y, s_a[1]);
                m_a[2] = fmaf(ra1[u], va[u].z, m_a[2]); s_a[2] = fmaf(ra1[u], va[u].z*va[u].z, s_a[2]);
                m_a[3] = fmaf(ra1[u], va[u].w, m_a[3]); s_a[3] = fmaf(ra1[u], va[u].w*va[u].w, s_a[3]);
                r1 += ra1[u];
                if (act2) {
                    m_b[0] = fmaf(ra2[u], vb[u].x, m_b[0]); s_b[0] = fmaf(ra2[u], vb[u].x*vb[u].x, s_b[0]);
                    m_b[1] = fmaf(ra2[u], vb[u].y, m_b[1]); s_b[1] = fmaf(ra2[u], vb[u].y*vb[u].y, s_b[1]);
                    m_b[2] = fmaf(ra2[u], vb[u].z, m_b[2]); s_b[2] = fmaf(ra2[u], vb[u].z*vb[u].z, s_b[2]);
                    m_b[3] = fmaf(ra2[u], vb[u].w, m_b[3]); s_b[3] = fmaf(ra2[u], vb[u].w*vb[u].w, s_b[3]);
                    r2 += ra2[u];
                }
            }
        }
        *(float4*)(pbm + wid*BBPS + lane*4) = make_float4(m_a[0],m_a[1],m_a[2],m_a[3]);
        *(float4*)(pbs + wid*BBPS + lane*4) = make_float4(s_a[0],s_a[1],s_a[2],s_a[3]);
        if (act2) {
            *(float4*)(pbm + wid*BBPS + (lane+32)*4) = make_float4(m_b[0],m_b[1],m_b[2],m_b[3]);
            *(float4*)(pbs + wid*BBPS + (lane+32)*4) = make_float4(s_b[0],s_b[1],s_b[2],s_b[3]);
        }
        if ((lane & 3) == 0) {
            pA[wid*17 + j1] = r1;
            if (act2) pA[wid*17 + j2] = r2;
        }
        __syncthreads();
        finalize(lam, NW, false);
        __syncthreads();
    }

    // Outputs
    if (WPOSE) {
        for (int t = tid; t < BBPS; t += NT) {
            poseOut[(((size_t)n*BBPS + t)*OH + oy)*OH + ox] =
                smu[t]*BN_SCALE*bng[t] + bnb[t];
        }
    }
    if (tid < BB) {
        if (FC)
            aOut[((size_t)n*(OH*OH) + lidx)*BB + tid] = sao[tid];
        else
            aOut[(((size_t)n*BB + tid)*OH + oy)*OH + ox] = sao[tid];
    }
}

// ---------------------------------------------------------------------------
__global__ void reduce_kernel(const float* __restrict__ afc, float* __restrict__ out)
{
    const int t = blockIdx.x*blockDim.x + threadIdx.x;
    if (t < 320) {
        const int n = t / 10, j = t % 10;
        float s = 0.f;
        for (int l = 0; l < 25; l++) s += afc[(n*25 + l)*10 + j];
        out[t] = s * (1.0f/25.0f);
    }
}

// ---------------------------------------------------------------------------
extern "C" void kernel_launch(void* const* d_in, const int* in_sizes, int n_in,
                              void* d_out, int out_size)
{
    const float* x       = (const float*)d_in[0];
    const float* conv1_w = (const float*)d_in[1];
    const float* bn1_g   = (const float*)d_in[2];
    const float* bn1_b   = (const float*)d_in[3];
    const float* conva_w = (const float*)d_in[4];
    const float* bna_g   = (const float*)d_in[5];
    const float* bna_b   = (const float*)d_in[6];
    const float* convp_w = (const float*)d_in[7];
    const float* bnp_g   = (const float*)d_in[8];
    const float* bnp_b   = (const float*)d_in[9];
    const float* W1      = (const float*)d_in[10];
    const float* bu1     = (const float*)d_in[11];
    const float* ba1     = (const float*)d_in[12];
    const float* bnc1_g  = (const float*)d_in[13];
    const float* bnc1_b  = (const float*)d_in[14];
    const float* W2      = (const float*)d_in[15];
    const float* bu2     = (const float*)d_in[16];
    const float* ba2     = (const float*)d_in[17];
    const float* bnc2_g  = (const float*)d_in[18];
    const float* bnc2_b  = (const float*)d_in[19];
    const float* Wfc     = (const float*)d_in[20];
    const float* bufc    = (const float*)d_in[21];
    const float* bafc    = (const float*)d_in[22];

    float *buf1, *bufA, *bufP, *bufA2, *bufP2, *bufA3, *bufP3, *bufFC;
    cudaGetSymbolAddress((void**)&buf1,  g_buf1);
    cudaGetSymbolAddress((void**)&bufA,  g_bufA);
    cudaGetSymbolAddress((void**)&bufP,  g_bufP);
    cudaGetSymbolAddress((void**)&bufA2, g_bufA2);
    cudaGetSymbolAddress((void**)&bufP2, g_bufP2);
    cudaGetSymbolAddress((void**)&bufA3, g_bufA3);
    cudaGetSymbolAddress((void**)&bufP3, g_bufP3);
    cudaGetSymbolAddress((void**)&bufFC, g_bufFC);

    // conv1 + bn
    conv1_kernel<<<dim3(32,16), 224>>>(x, conv1_w, bn1_g, bn1_b, buf1);

    // conv3: convp tiles (y<8, NCO=2) + conva (y==8, sigmoid) in one launch
    const size_t c3smem = 64*196*sizeof(float);
    cudaFuncSetAttribute((const void*)conv3_both_kernel,
                         cudaFuncAttributeMaxDynamicSharedMemorySize, (int)c3smem);
    conv3_both_kernel<<<dim3(32,9), 192, c3smem>>>(
        buf1, convp_w, bnp_g, bnp_b, conva_w, bna_g, bna_b, bufP, bufA);

    // EM1/EM2: fp16 votes, NT=256, 2 CTAs/SM
    {
        constexpr int NT = 256, NW = NT/32;
        constexpr int KKA = 144, BBPS = 256, VSTH = BBPS + 8;
        const size_t smh = (size_t)KKA*VSTH*2
                         + (size_t)(2*NW*BBPS + 2*BBPS + KKA + KKA*16
                                    + NW*17 + 2*16) * sizeof(float);
        // EM1: 12x12 -> 6x6, k=3 s=2 p=1 (bnc1 fused)
        {
            auto fn = em_kernel<NT,2,true,16,16,3,2,1,12,6,true,false>;
            cudaFuncSetAttribute(fn, cudaFuncAttributeMaxDynamicSharedMemorySize, (int)smh);
            fn<<<dim3(36,32), NT, smh>>>(bufA, bufP, W1, bu1, ba1, bnc1_g, bnc1_b, bufA2, bufP2);
        }
        // EM2: 6x6 -> 6x6, k=3 s=1 p=1 (bnc2 fused)
        {
            auto fn = em_kernel<NT,2,true,16,16,3,1,1,6,6,true,false>;
            cudaFuncSetAttribute(fn, cudaFuncAttributeMaxDynamicSharedMemorySize, (int)smh);
            fn<<<dim3(36,32), NT, smh>>>(bufA2, bufP2, W2, bu2, ba2, bnc2_g, bnc2_b, bufA3, bufP3);
        }
    }

    // EM3 (class caps): 6x6 -> 5x5, k=4 s=1 p=1, A=16 B=10  (fp32, NT=512)
    {
        constexpr int NT = 512, NW = NT/32;
        constexpr int KKA = 256, BBPS = 160, VST = 164;
        const size_t sm3 = (size_t)(KKA*VST + 2*NW*BBPS + 2*BBPS
                                    + KKA + KKA*16 + NW*17 + 2*10) * sizeof(float);
        auto fn = em_kernel<NT,1,false,16,10,4,1,1,6,5,false,true>;
        cudaFuncSetAttribute(fn, cudaFuncAttributeMaxDynamicSharedMemorySize, (int)sm3);
        fn<<<dim3(25,32), NT, sm3>>>(bufA3, bufP3, Wfc, bufc, bafc, nullptr, nullptr, bufFC, nullptr);
    }

    // mean over spatial
    reduce_kernel<<<1, 320>>>(bufFC, (float*)d_out);
}